// round 7
// baseline (speedup 1.0000x reference)
#include <cuda_runtime.h>
#include <cuda_fp16.h>
#include <cstdint>
#include <math.h>

// ---------------------------------------------------------------------------
// GAT 4-layer stack on GB300, round 7:
//  - fp16 mma.sync m16n8k16 GEMM, fp32 accum, cp.async double-buffered
//  - h fp16 end-to-end
//  - softmax FUSED into aggregation (warp per (dst,head), 2-pass:
//    max, then exp+num+den in one sweep; divide at end). No alpha array,
//    no edge_softmax kernel.
//  - shuffle-based CSR scan (fewer barriers)
// ---------------------------------------------------------------------------

#define NN      30000
#define E_RAW   480000
#define E_TOT   (E_RAW + NN)
#define MAXF    512
#define NEG_SLOPE 0.2f

// ---- scratch (device globals) ---------------------------------------------
__device__ __half g_hA[NN * MAXF];              // fp16 activations (GEMM in)
__device__ __half g_hB[NN * MAXF];              // fp16 h (GEMM out)
__device__ __half g_wt[540672];                 // all transposed fp16 weights
__device__ float  g_as[NN * 4];
__device__ float  g_ad[NN * 4];
__device__ int    g_deg[NN];
__device__ int    g_rowptr[NN + 1];
__device__ int    g_cursor[NN];
__device__ int    g_csrsrc[E_TOT];
__device__ int    g_is64;

// ---------------------------------------------------------------------------
// edge_index dtype detection (int32 vs int64)
// ---------------------------------------------------------------------------
__global__ void detect64_kernel(const int* __restrict__ words, int* flag) {
    if (threadIdx.x == 0 && blockIdx.x == 0) {
        int any = 0;
        #pragma unroll 4
        for (int i = 0; i < 256; i++) any |= words[2 * i + 1];
        *flag = (any == 0) ? 1 : 0;
    }
}

__device__ __forceinline__ void get_edge(const void* ei, int e, int is64,
                                         int& src, int& dst) {
    if (e >= E_RAW) { src = dst = e - E_RAW; return; }
    if (is64) {
        const long long* p = (const long long*)ei;
        src = (int)p[e];
        dst = (int)p[E_RAW + e];
    } else {
        const int* p = (const int*)ei;
        src = p[e];
        dst = p[E_RAW + e];
    }
}

// ---- CSR build ------------------------------------------------------------
__global__ void count_deg_kernel(const void* __restrict__ ei,
                                 const int* __restrict__ flag,
                                 int* __restrict__ deg) {
    int e = blockIdx.x * blockDim.x + threadIdx.x;
    if (e >= E_TOT) return;
    int src, dst;
    get_edge(ei, e, *flag, src, dst);
    atomicAdd(&deg[dst], 1);
}

// shuffle-based block scan, 1024 threads, 3 barriers per 1024-chunk
__global__ void scan_kernel(const int* __restrict__ deg,
                            int* __restrict__ rowptr, int n) {
    __shared__ int warpsums[32];
    __shared__ int carry_s;
    int t = threadIdx.x;
    int lane = t & 31;
    int w = t >> 5;
    if (t == 0) carry_s = 0;
    __syncthreads();
    for (int base = 0; base < n; base += 1024) {
        int i = base + t;
        int v = (i < n) ? deg[i] : 0;
        int x = v;
        #pragma unroll
        for (int o = 1; o < 32; o <<= 1) {
            int u = __shfl_up_sync(0xffffffffu, x, o);
            if (lane >= o) x += u;
        }
        if (lane == 31) warpsums[w] = x;
        __syncthreads();
        if (w == 0) {
            int s = warpsums[lane];
            #pragma unroll
            for (int o = 1; o < 32; o <<= 1) {
                int u = __shfl_up_sync(0xffffffffu, s, o);
                if (lane >= o) s += u;
            }
            warpsums[lane] = s;
        }
        __syncthreads();
        int woff = (w > 0) ? warpsums[w - 1] : 0;
        int incl = x + woff + carry_s;
        if (i < n) rowptr[i] = incl - v;   // exclusive
        __syncthreads();
        if (t == 1023) carry_s = incl;
        __syncthreads();
    }
    if (t == 0) rowptr[n] = carry_s;
}

__global__ void fill_csr_kernel(const void* __restrict__ ei,
                                const int* __restrict__ flag,
                                int* __restrict__ cursor,
                                int* __restrict__ csrsrc) {
    int e = blockIdx.x * blockDim.x + threadIdx.x;
    if (e >= E_TOT) return;
    int src, dst;
    get_edge(ei, e, *flag, src, dst);
    int pos = atomicAdd(&cursor[dst], 1);
    csrsrc[pos] = src;
}

// ---- prep: fp32 -> fp16 convert, weight transpose -------------------------
__global__ void f2h_kernel(const float* __restrict__ in,
                           __half* __restrict__ out, int n) {
    int i = blockIdx.x * blockDim.x + threadIdx.x;
    int i4 = i * 4;
    if (i4 + 3 < n) {
        float4 v = *(const float4*)&in[i4];
        __half2 lo = __floats2half2_rn(v.x, v.y);
        __half2 hi = __floats2half2_rn(v.z, v.w);
        *(__half2*)&out[i4] = lo;
        *(__half2*)&out[i4 + 2] = hi;
    } else {
        for (int j = i4; j < n; j++) out[j] = __float2half_rn(in[j]);
    }
}

// W[K][N] fp32 -> Wt[N][K] fp16
__global__ void transpose_w_kernel(const float* __restrict__ W,
                                   __half* __restrict__ Wt, int K, int N) {
    __shared__ float tile[32][33];
    int k0 = blockIdx.y * 32, n0 = blockIdx.x * 32;
    int tx = threadIdx.x, ty = threadIdx.y;   // 32 x 8
    for (int i = ty; i < 32; i += 8) {
        int k = k0 + i, n = n0 + tx;
        tile[i][tx] = (k < K && n < N) ? W[(size_t)k * N + n] : 0.f;
    }
    __syncthreads();
    for (int i = ty; i < 32; i += 8) {
        int n = n0 + i, k = k0 + tx;
        if (n < N && k < K)
            Wt[(size_t)n * K + k] = __float2half_rn(tile[tx][i]);
    }
}

// ---------------------------------------------------------------------------
// fp16 tensor-core GEMM: C16[MxN] = round_f16(A16[MxK] * Wt16[NxK]^T)
// ---------------------------------------------------------------------------
#define TBM 128
#define TBN 128
#define TBK 32
#define SAH 40

__device__ __forceinline__ void cp16(unsigned int smem, const void* gptr, int sz) {
    asm volatile("cp.async.cg.shared.global [%0], [%1], 16, %2;\n"
                 :: "r"(smem), "l"(gptr), "r"(sz));
}

__device__ __forceinline__ unsigned int smem_u32(const void* p) {
    return (unsigned int)__cvta_generic_to_shared(p);
}

__device__ __forceinline__ void mma_f16(float* d, const unsigned* a,
                                        const unsigned* b) {
    asm volatile(
        "mma.sync.aligned.m16n8k16.row.col.f32.f16.f16.f32 "
        "{%0,%1,%2,%3}, {%4,%5,%6,%7}, {%8,%9}, {%0,%1,%2,%3};\n"
        : "+f"(d[0]), "+f"(d[1]), "+f"(d[2]), "+f"(d[3])
        : "r"(a[0]), "r"(a[1]), "r"(a[2]), "r"(a[3]),
          "r"(b[0]), "r"(b[1]));
}

__global__ __launch_bounds__(256, 2)
void h16gemm_kernel(const __half* __restrict__ A, const __half* __restrict__ Bt,
                    __half* __restrict__ C, int M, int N, int K) {
    __shared__ __half As[2][TBM * SAH];
    __shared__ __half Bs[2][TBN * SAH];

    int tid  = threadIdx.x;
    int bm   = blockIdx.y * TBM;
    int bn   = blockIdx.x * TBN;
    int warp = tid >> 5;
    int lane = tid & 31;
    int wm   = (warp & 1) * 64;
    int wn   = (warp >> 1) * 32;
    int r    = lane >> 2;
    int c    = lane & 3;

    float acc[4][4][4];
    #pragma unroll
    for (int mi = 0; mi < 4; mi++)
        #pragma unroll
        for (int ni = 0; ni < 4; ni++)
            #pragma unroll
            for (int q = 0; q < 4; q++) acc[mi][ni][q] = 0.f;

    int row0 = tid >> 1;
    int kc0  = (tid & 1) * 2;

    int niter = K / TBK;

    auto stage = [&](int buf, int k0) {
        #pragma unroll
        for (int j = 0; j < 2; j++) {
            int kc = kc0 + j;
            int smoff = (row0 * SAH + kc * 8) * 2;
            int ra = bm + row0;
            const __half* ga = A + (size_t)(ra < M ? ra : 0) * K + k0 + kc * 8;
            cp16(smem_u32(&As[buf][0]) + smoff, ga, ra < M ? 16 : 0);
            int rb = bn + row0;
            const __half* gb = Bt + (size_t)(rb < N ? rb : 0) * K + k0 + kc * 8;
            cp16(smem_u32(&Bs[buf][0]) + smoff, gb, rb < N ? 16 : 0);
        }
        asm volatile("cp.async.commit_group;\n");
    };

    stage(0, 0);

    for (int it = 0; it < niter; it++) {
        if (it + 1 < niter) {
            stage((it + 1) & 1, (it + 1) * TBK);
            asm volatile("cp.async.wait_group 1;\n");
        } else {
            asm volatile("cp.async.wait_group 0;\n");
        }
        __syncthreads();

        int buf = it & 1;
        #pragma unroll
        for (int kk = 0; kk < 2; kk++) {
            int kb = kk * 16;
            unsigned af[4][4];
            #pragma unroll
            for (int mi = 0; mi < 4; mi++) {
                const __half* ap = &As[buf][(wm + mi * 16 + r) * SAH + kb + 2 * c];
                af[mi][0] = *(const unsigned*)(ap);
                af[mi][1] = *(const unsigned*)(ap + 8 * SAH);
                af[mi][2] = *(const unsigned*)(ap + 8);
                af[mi][3] = *(const unsigned*)(ap + 8 * SAH + 8);
            }
            unsigned bf[4][2];
            #pragma unroll
            for (int ni = 0; ni < 4; ni++) {
                const __half* bp = &Bs[buf][(wn + ni * 8 + r) * SAH + kb + 2 * c];
                bf[ni][0] = *(const unsigned*)(bp);
                bf[ni][1] = *(const unsigned*)(bp + 8);
            }
            #pragma unroll
            for (int mi = 0; mi < 4; mi++)
                #pragma unroll
                for (int ni = 0; ni < 4; ni++)
                    mma_f16(acc[mi][ni], af[mi], bf[ni]);
        }
        __syncthreads();
    }

    #pragma unroll
    for (int mi = 0; mi < 4; mi++) {
        int m0 = bm + wm + mi * 16 + r;
        #pragma unroll
        for (int ni = 0; ni < 4; ni++) {
            int n0 = bn + wn + ni * 8 + 2 * c;
            if (n0 < N) {
                if (m0 < M) {
                    __half2 v = __floats2half2_rn(acc[mi][ni][0], acc[mi][ni][1]);
                    *(__half2*)&C[(size_t)m0 * N + n0] = v;
                }
                if (m0 + 8 < M) {
                    __half2 v = __floats2half2_rn(acc[mi][ni][2], acc[mi][ni][3]);
                    *(__half2*)&C[(size_t)(m0 + 8) * N + n0] = v;
                }
            }
        }
    }
}

// ---- per-node attention logits (fp16 h, fp32 accum) -----------------------
__global__ void node_alpha_kernel(const __half* __restrict__ h,
                                  const float* __restrict__ a_s,
                                  const float* __restrict__ a_d,
                                  float* __restrict__ out_s,
                                  float* __restrict__ out_d,
                                  int H, int C) {
    int warp = (blockIdx.x * blockDim.x + threadIdx.x) >> 5;
    int lane = threadIdx.x & 31;
    if (warp >= NN * H) return;
    int n = warp / H;
    int hd = warp - n * H;
    const __half* hp = h + (size_t)n * H * C + (size_t)hd * C;
    const float* asv = a_s + (size_t)hd * C;
    const float* adv = a_d + (size_t)hd * C;
    float s = 0.f, d = 0.f;
    for (int cc = lane * 2; cc < C; cc += 64) {
        float2 v = __half22float2(*(const __half2*)&hp[cc]);
        s = fmaf(v.x, asv[cc], s);
        s = fmaf(v.y, asv[cc + 1], s);
        d = fmaf(v.x, adv[cc], d);
        d = fmaf(v.y, adv[cc + 1], d);
    }
    #pragma unroll
    for (int o = 16; o > 0; o >>= 1) {
        s += __shfl_xor_sync(0xffffffffu, s, o);
        d += __shfl_xor_sync(0xffffffffu, d, o);
    }
    if (lane == 0) {
        out_s[n * H + hd] = s;
        out_d[n * H + hd] = d;
    }
}

// ---- fused softmax + aggregation ------------------------------------------
// warp per (dst, head). Pass 1: max over incoming edges (lanes over edges).
// Pass 2: num += exp(e-mx)*h[src], den += exp(e-mx); out = num/den + b, relu.
__device__ __forceinline__ float leaky(float x) {
    return x > 0.f ? x : NEG_SLOPE * x;
}

template <int PERLANE, bool F16OUT>
__global__ __launch_bounds__(256)
void fused_sm_agg_kernel(const __half* __restrict__ h,
                         const float* __restrict__ as_,
                         const float* __restrict__ ad_,
                         const int* __restrict__ rowptr,
                         const int* __restrict__ csrsrc,
                         const float* __restrict__ bias,
                         float* __restrict__ out32,
                         __half* __restrict__ out16,
                         int H, int C) {
    int warp = (blockIdx.x * blockDim.x + threadIdx.x) >> 5;
    int lane = threadIdx.x & 31;
    if (warp >= NN * H) return;
    int d = warp / H;
    int hd = warp - d * H;
    int s0 = rowptr[d], s1 = rowptr[d + 1];
    float adv = ad_[d * H + hd];

    // pass 1: max (lanes parallel over edges)
    float mx = -3.0e38f;
    for (int p = s0 + lane; p < s1; p += 32)
        mx = fmaxf(mx, leaky(as_[csrsrc[p] * H + hd] + adv));
    #pragma unroll
    for (int o = 16; o > 0; o >>= 1)
        mx = fmaxf(mx, __shfl_xor_sync(0xffffffffu, mx, o));

    // pass 2: num/den (lanes over features, edges sequential, 2-unrolled)
    int HC = H * C;
    int fbase = hd * C + lane * PERLANE;
    float den = 0.f;
    float acc[PERLANE];
    #pragma unroll
    for (int q = 0; q < PERLANE; q++) acc[q] = 0.f;

    int p = s0;
    for (; p + 1 < s1; p += 2) {
        int srcA = csrsrc[p];
        int srcB = csrsrc[p + 1];
        float aA = expf(leaky(as_[srcA * H + hd] + adv) - mx);
        float aB = expf(leaky(as_[srcB * H + hd] + adv) - mx);
        den += aA + aB;
        if (PERLANE == 4) {
            uint2 rA = *(const uint2*)&h[(size_t)srcA * HC + fbase];
            uint2 rB = *(const uint2*)&h[(size_t)srcB * HC + fbase];
            float2 a0 = __half22float2(*(__half2*)&rA.x);
            float2 a1 = __half22float2(*(__half2*)&rA.y);
            float2 b0 = __half22float2(*(__half2*)&rB.x);
            float2 b1 = __half22float2(*(__half2*)&rB.y);
            acc[0] = fmaf(a0.x, aA, fmaf(b0.x, aB, acc[0]));
            acc[1] = fmaf(a0.y, aA, fmaf(b0.y, aB, acc[1]));
            acc[2] = fmaf(a1.x, aA, fmaf(b1.x, aB, acc[2]));
            acc[3] = fmaf(a1.y, aA, fmaf(b1.y, aB, acc[3]));
        } else {
            unsigned rA = *(const unsigned*)&h[(size_t)srcA * HC + fbase];
            unsigned rB = *(const unsigned*)&h[(size_t)srcB * HC + fbase];
            float2 a0 = __half22float2(*(__half2*)&rA);
            float2 b0 = __half22float2(*(__half2*)&rB);
            acc[0] = fmaf(a0.x, aA, fmaf(b0.x, aB, acc[0]));
            acc[1] = fmaf(a0.y, aA, fmaf(b0.y, aB, acc[1]));
        }
    }
    if (p < s1) {
        int src = csrsrc[p];
        float a = expf(leaky(as_[src * H + hd] + adv) - mx);
        den += a;
        if (PERLANE == 4) {
            uint2 raw = *(const uint2*)&h[(size_t)src * HC + fbase];
            float2 v0 = __half22float2(*(__half2*)&raw.x);
            float2 v1 = __half22float2(*(__half2*)&raw.y);
            acc[0] = fmaf(v0.x, a, acc[0]);
            acc[1] = fmaf(v0.y, a, acc[1]);
            acc[2] = fmaf(v1.x, a, acc[2]);
            acc[3] = fmaf(v1.y, a, acc[3]);
        } else {
            unsigned raw = *(const unsigned*)&h[(size_t)src * HC + fbase];
            float2 v0 = __half22float2(*(__half2*)&raw);
            acc[0] = fmaf(v0.x, a, acc[0]);
            acc[1] = fmaf(v0.y, a, acc[1]);
        }
    }

    float inv = 1.f / den;
    if (PERLANE == 4) {
        float4 b = *(const float4*)&bias[fbase];
        float o0 = fmaxf(fmaf(acc[0], inv, b.x), 0.f);
        float o1 = fmaxf(fmaf(acc[1], inv, b.y), 0.f);
        float o2 = fmaxf(fmaf(acc[2], inv, b.z), 0.f);
        float o3 = fmaxf(fmaf(acc[3], inv, b.w), 0.f);
        if (F16OUT) {
            uint2 packed;
            *(__half2*)&packed.x = __floats2half2_rn(o0, o1);
            *(__half2*)&packed.y = __floats2half2_rn(o2, o3);
            *(uint2*)&out16[(size_t)d * HC + fbase] = packed;
        } else {
            *(float4*)&out32[(size_t)d * HC + fbase] = make_float4(o0, o1, o2, o3);
        }
    } else {
        float2 b = *(const float2*)&bias[fbase];
        float o0 = fmaxf(fmaf(acc[0], inv, b.x), 0.f);
        float o1 = fmaxf(fmaf(acc[1], inv, b.y), 0.f);
        if (F16OUT) {
            unsigned packed;
            *(__half2*)&packed = __floats2half2_rn(o0, o1);
            *(unsigned*)&out16[(size_t)d * HC + fbase] = packed;
        } else {
            *(float2*)&out32[(size_t)d * HC + fbase] = make_float2(o0, o1);
        }
    }
}

// ---------------------------------------------------------------------------
// host side
// ---------------------------------------------------------------------------
static inline void run_gemm(const __half* A, const __half* Bt, __half* C,
                            int M, int N, int K) {
    dim3 grid((N + TBN - 1) / TBN, (M + TBM - 1) / TBM);
    h16gemm_kernel<<<grid, 256>>>(A, Bt, C, M, N, K);
}

static inline void run_transpose(const float* W, __half* Wt, int K, int N) {
    dim3 grid((N + 31) / 32, (K + 31) / 32);
    transpose_w_kernel<<<grid, dim3(32, 8)>>>(W, Wt, K, N);
}

extern "C" void kernel_launch(void* const* d_in, const int* in_sizes, int n_in,
                              void* d_out, int out_size) {
    const float* x   = (const float*)d_in[0];
    const void*  ei  = d_in[1];
    const float* W1  = (const float*)d_in[2];
    const float* a1s = (const float*)d_in[3];
    const float* a1d = (const float*)d_in[4];
    const float* b1  = (const float*)d_in[5];
    const float* W2  = (const float*)d_in[6];
    const float* a2s = (const float*)d_in[7];
    const float* a2d = (const float*)d_in[8];
    const float* b2  = (const float*)d_in[9];
    const float* W3  = (const float*)d_in[10];
    const float* a3s = (const float*)d_in[11];
    const float* a3d = (const float*)d_in[12];
    const float* b3  = (const float*)d_in[13];
    const float* W4  = (const float*)d_in[14];
    const float* a4s = (const float*)d_in[15];
    const float* a4d = (const float*)d_in[16];
    const float* b4  = (const float*)d_in[17];
    float* out = (float*)d_out;

    float *asb, *adb;
    __half *hA, *hB, *wt;
    int *deg, *rowptr, *cursor, *csrsrc, *is64;
    cudaGetSymbolAddress((void**)&hA, g_hA);
    cudaGetSymbolAddress((void**)&hB, g_hB);
    cudaGetSymbolAddress((void**)&wt, g_wt);
    cudaGetSymbolAddress((void**)&asb, g_as);
    cudaGetSymbolAddress((void**)&adb, g_ad);
    cudaGetSymbolAddress((void**)&deg, g_deg);
    cudaGetSymbolAddress((void**)&rowptr, g_rowptr);
    cudaGetSymbolAddress((void**)&cursor, g_cursor);
    cudaGetSymbolAddress((void**)&csrsrc, g_csrsrc);
    cudaGetSymbolAddress((void**)&is64, g_is64);

    __half* wt1 = wt;                     // [512][256]
    __half* wt2 = wt + 131072;            // [512][512]
    __half* wt3 = wt + 131072 + 262144;   // [256][512]
    __half* wt4 = wt + 131072 + 262144 + 131072;  // [64][256]

    // ---- prep: CSR + dtype conversions ----
    cudaMemsetAsync(deg, 0, NN * sizeof(int));
    detect64_kernel<<<1, 32>>>((const int*)ei, is64);
    count_deg_kernel<<<(E_TOT + 255) / 256, 256>>>(ei, is64, deg);
    scan_kernel<<<1, 1024>>>(deg, rowptr, NN);
    cudaMemcpyAsync(cursor, rowptr, NN * sizeof(int), cudaMemcpyDeviceToDevice);
    fill_csr_kernel<<<(E_TOT + 255) / 256, 256>>>(ei, is64, cursor, csrsrc);

    f2h_kernel<<<(NN * 256 / 4 + 255) / 256, 256>>>(x, hA, NN * 256);
    run_transpose(W1, wt1, 256, 512);
    run_transpose(W2, wt2, 512, 512);
    run_transpose(W3, wt3, 512, 256);
    run_transpose(W4, wt4, 256, 64);

    auto nblocks_warps = [](int warps) { return (warps + 7) / 8; };

    // ---- layer 1: 256 -> 4x128 ----
    run_gemm(hA, wt1, hB, NN, 512, 256);
    node_alpha_kernel<<<nblocks_warps(NN * 4), 256>>>(hB, a1s, a1d, asb, adb, 4, 128);
    fused_sm_agg_kernel<4, true><<<nblocks_warps(NN * 4), 256>>>(
        hB, asb, adb, rowptr, csrsrc, b1, nullptr, hA, 4, 128);

    // ---- layer 2: 512 -> 4x128 ----
    run_gemm(hA, wt2, hB, NN, 512, 512);
    node_alpha_kernel<<<nblocks_warps(NN * 4), 256>>>(hB, a2s, a2d, asb, adb, 4, 128);
    fused_sm_agg_kernel<4, true><<<nblocks_warps(NN * 4), 256>>>(
        hB, asb, adb, rowptr, csrsrc, b2, nullptr, hA, 4, 128);

    // ---- layer 3: 512 -> 4x64 ----
    run_gemm(hA, wt3, hB, NN, 256, 512);
    node_alpha_kernel<<<nblocks_warps(NN * 4), 256>>>(hB, a3s, a3d, asb, adb, 4, 64);
    fused_sm_agg_kernel<2, true><<<nblocks_warps(NN * 4), 256>>>(
        hB, asb, adb, rowptr, csrsrc, b3, nullptr, hA, 4, 64);

    // ---- layer 4: 256 -> 1x64, concat=False ----
    run_gemm(hA, wt4, hB, NN, 64, 256);
    node_alpha_kernel<<<nblocks_warps(NN * 1), 256>>>(hB, a4s, a4d, asb, adb, 1, 64);
    fused_sm_agg_kernel<2, false><<<nblocks_warps(NN * 1), 256>>>(
        hB, asb, adb, rowptr, csrsrc, b4, out, nullptr, 1, 64);

    (void)in_sizes; (void)n_in; (void)out_size;
}

// round 8
// speedup vs baseline: 1.1856x; 1.1856x over previous
#include <cuda_runtime.h>
#include <cuda_fp16.h>
#include <cstdint>
#include <math.h>

// ---------------------------------------------------------------------------
// GAT 4-layer stack on GB300, round 8 (round-6 structure + 2 changes):
//  - fp16 mma.sync m16n8k16 GEMM, cp.async double-buffered, M-padded (no M checks)
//  - head-combined softmax: warp/dst, float4 as-gather once, e staged in alpha
//  - aggregate: round-6 version (uint2 fp16 gather, 2-edge unroll)
// ---------------------------------------------------------------------------

#define NN      30000
#define NPAD    30080
#define E_RAW   480000
#define E_TOT   (E_RAW + NN)
#define MAXF    512
#define NEG_SLOPE 0.2f

// ---- scratch (device globals; zero-initialized at load) -------------------
__device__ __half g_hA[NPAD * MAXF];            // fp16 activations ping
__device__ __half g_hB[NPAD * MAXF];            // fp16 activations pong
__device__ __half g_wt[540672];                 // transposed fp16 weights
__device__ float  g_as[NN * 4];
__device__ float  g_ad[NN * 4];
__device__ float  g_alpha[(size_t)E_TOT * 4];   // e / ex / alpha (in-place)
__device__ int    g_deg[NN];
__device__ int    g_rowptr[NN + 1];
__device__ int    g_cursor[NN];
__device__ int    g_csrsrc[E_TOT];
__device__ int    g_is64;

// ---------------------------------------------------------------------------
// edge_index dtype detection (int32 vs int64)
// ---------------------------------------------------------------------------
__global__ void detect64_kernel(const int* __restrict__ words, int* flag) {
    if (threadIdx.x == 0 && blockIdx.x == 0) {
        int any = 0;
        #pragma unroll 4
        for (int i = 0; i < 256; i++) any |= words[2 * i + 1];
        *flag = (any == 0) ? 1 : 0;
    }
}

__device__ __forceinline__ void get_edge(const void* ei, int e, int is64,
                                         int& src, int& dst) {
    if (e >= E_RAW) { src = dst = e - E_RAW; return; }
    if (is64) {
        const long long* p = (const long long*)ei;
        src = (int)p[e];
        dst = (int)p[E_RAW + e];
    } else {
        const int* p = (const int*)ei;
        src = p[e];
        dst = p[E_RAW + e];
    }
}

// ---- CSR build ------------------------------------------------------------
__global__ void count_deg_kernel(const void* __restrict__ ei,
                                 const int* __restrict__ flag,
                                 int* __restrict__ deg) {
    int e = blockIdx.x * blockDim.x + threadIdx.x;
    if (e >= E_TOT) return;
    int src, dst;
    get_edge(ei, e, *flag, src, dst);
    atomicAdd(&deg[dst], 1);
}

// shuffle-based block scan
__global__ void scan_kernel(const int* __restrict__ deg,
                            int* __restrict__ rowptr, int n) {
    __shared__ int warpsums[32];
    __shared__ int carry_s;
    int t = threadIdx.x;
    int lane = t & 31;
    int w = t >> 5;
    if (t == 0) carry_s = 0;
    __syncthreads();
    for (int base = 0; base < n; base += 1024) {
        int i = base + t;
        int v = (i < n) ? deg[i] : 0;
        int x = v;
        #pragma unroll
        for (int o = 1; o < 32; o <<= 1) {
            int u = __shfl_up_sync(0xffffffffu, x, o);
            if (lane >= o) x += u;
        }
        if (lane == 31) warpsums[w] = x;
        __syncthreads();
        if (w == 0) {
            int s = warpsums[lane];
            #pragma unroll
            for (int o = 1; o < 32; o <<= 1) {
                int u = __shfl_up_sync(0xffffffffu, s, o);
                if (lane >= o) s += u;
            }
            warpsums[lane] = s;
        }
        __syncthreads();
        int woff = (w > 0) ? warpsums[w - 1] : 0;
        int incl = x + woff + carry_s;
        if (i < n) rowptr[i] = incl - v;
        __syncthreads();
        if (t == 1023) carry_s = incl;
        __syncthreads();
    }
    if (t == 0) rowptr[n] = carry_s;
}

__global__ void fill_csr_kernel(const void* __restrict__ ei,
                                const int* __restrict__ flag,
                                int* __restrict__ cursor,
                                int* __restrict__ csrsrc) {
    int e = blockIdx.x * blockDim.x + threadIdx.x;
    if (e >= E_TOT) return;
    int src, dst;
    get_edge(ei, e, *flag, src, dst);
    int pos = atomicAdd(&cursor[dst], 1);
    csrsrc[pos] = src;
}

// ---- prep: fp32 -> fp16 convert, weight transpose -------------------------
__global__ void f2h_kernel(const float* __restrict__ in,
                           __half* __restrict__ out, int n) {
    int i = blockIdx.x * blockDim.x + threadIdx.x;
    int i4 = i * 4;
    if (i4 + 3 < n) {
        float4 v = *(const float4*)&in[i4];
        __half2 lo = __floats2half2_rn(v.x, v.y);
        __half2 hi = __floats2half2_rn(v.z, v.w);
        *(__half2*)&out[i4] = lo;
        *(__half2*)&out[i4 + 2] = hi;
    } else {
        for (int j = i4; j < n; j++) out[j] = __float2half_rn(in[j]);
    }
}

// W[K][N] fp32 -> Wt[N][K] fp16
__global__ void transpose_w_kernel(const float* __restrict__ W,
                                   __half* __restrict__ Wt, int K, int N) {
    __shared__ float tile[32][33];
    int k0 = blockIdx.y * 32, n0 = blockIdx.x * 32;
    int tx = threadIdx.x, ty = threadIdx.y;
    for (int i = ty; i < 32; i += 8) {
        int k = k0 + i, n = n0 + tx;
        tile[i][tx] = (k < K && n < N) ? W[(size_t)k * N + n] : 0.f;
    }
    __syncthreads();
    for (int i = ty; i < 32; i += 8) {
        int n = n0 + i, k = k0 + tx;
        if (n < N && k < K)
            Wt[(size_t)n * K + k] = __float2half_rn(tile[tx][i]);
    }
}

// ---------------------------------------------------------------------------
// fp16 tensor-core GEMM: C16[M_pad x N] = A16[M_pad x K] * Wt16[N x K]^T
// M padded to 128 multiple: NO M bounds anywhere.
// ---------------------------------------------------------------------------
#define TBM 128
#define TBN 128
#define TBK 32
#define SAH 40

__device__ __forceinline__ void cp16(unsigned int smem, const void* gptr, int sz) {
    asm volatile("cp.async.cg.shared.global [%0], [%1], 16, %2;\n"
                 :: "r"(smem), "l"(gptr), "r"(sz));
}

__device__ __forceinline__ unsigned int smem_u32(const void* p) {
    return (unsigned int)__cvta_generic_to_shared(p);
}

__device__ __forceinline__ void mma_f16(float* d, const unsigned* a,
                                        const unsigned* b) {
    asm volatile(
        "mma.sync.aligned.m16n8k16.row.col.f32.f16.f16.f32 "
        "{%0,%1,%2,%3}, {%4,%5,%6,%7}, {%8,%9}, {%0,%1,%2,%3};\n"
        : "+f"(d[0]), "+f"(d[1]), "+f"(d[2]), "+f"(d[3])
        : "r"(a[0]), "r"(a[1]), "r"(a[2]), "r"(a[3]),
          "r"(b[0]), "r"(b[1]));
}

__global__ __launch_bounds__(256, 2)
void h16gemm_kernel(const __half* __restrict__ A, const __half* __restrict__ Bt,
                    __half* __restrict__ C, int N, int K) {
    __shared__ __half As[2][TBM * SAH];
    __shared__ __half Bs[2][TBN * SAH];

    int tid  = threadIdx.x;
    int bm   = blockIdx.y * TBM;
    int bn   = blockIdx.x * TBN;
    int warp = tid >> 5;
    int lane = tid & 31;
    int wm   = (warp & 1) * 64;
    int wn   = (warp >> 1) * 32;
    int r    = lane >> 2;
    int c    = lane & 3;

    float acc[4][4][4];
    #pragma unroll
    for (int mi = 0; mi < 4; mi++)
        #pragma unroll
        for (int ni = 0; ni < 4; ni++)
            #pragma unroll
            for (int q = 0; q < 4; q++) acc[mi][ni][q] = 0.f;

    int row0 = tid >> 1;
    int kc0  = (tid & 1) * 2;

    int niter = K / TBK;

    auto stage = [&](int buf, int k0) {
        #pragma unroll
        for (int j = 0; j < 2; j++) {
            int kc = kc0 + j;
            int smoff = (row0 * SAH + kc * 8) * 2;
            const __half* ga = A + (size_t)(bm + row0) * K + k0 + kc * 8;
            cp16(smem_u32(&As[buf][0]) + smoff, ga, 16);
            int rb = bn + row0;
            const __half* gb = Bt + (size_t)(rb < N ? rb : 0) * K + k0 + kc * 8;
            cp16(smem_u32(&Bs[buf][0]) + smoff, gb, rb < N ? 16 : 0);
        }
        asm volatile("cp.async.commit_group;\n");
    };

    stage(0, 0);

    for (int it = 0; it < niter; it++) {
        if (it + 1 < niter) {
            stage((it + 1) & 1, (it + 1) * TBK);
            asm volatile("cp.async.wait_group 1;\n");
        } else {
            asm volatile("cp.async.wait_group 0;\n");
        }
        __syncthreads();

        int buf = it & 1;
        #pragma unroll
        for (int kk = 0; kk < 2; kk++) {
            int kb = kk * 16;
            unsigned af[4][4];
            #pragma unroll
            for (int mi = 0; mi < 4; mi++) {
                const __half* ap = &As[buf][(wm + mi * 16 + r) * SAH + kb + 2 * c];
                af[mi][0] = *(const unsigned*)(ap);
                af[mi][1] = *(const unsigned*)(ap + 8 * SAH);
                af[mi][2] = *(const unsigned*)(ap + 8);
                af[mi][3] = *(const unsigned*)(ap + 8 * SAH + 8);
            }
            unsigned bf[4][2];
            #pragma unroll
            for (int ni = 0; ni < 4; ni++) {
                const __half* bp = &Bs[buf][(wn + ni * 8 + r) * SAH + kb + 2 * c];
                bf[ni][0] = *(const unsigned*)(bp);
                bf[ni][1] = *(const unsigned*)(bp + 8);
            }
            #pragma unroll
            for (int mi = 0; mi < 4; mi++)
                #pragma unroll
                for (int ni = 0; ni < 4; ni++)
                    mma_f16(acc[mi][ni], af[mi], bf[ni]);
        }
        __syncthreads();
    }

    #pragma unroll
    for (int mi = 0; mi < 4; mi++) {
        int m0 = bm + wm + mi * 16 + r;
        #pragma unroll
        for (int ni = 0; ni < 4; ni++) {
            int n0 = bn + wn + ni * 8 + 2 * c;
            if (n0 < N) {
                __half2 v0 = __floats2half2_rn(acc[mi][ni][0], acc[mi][ni][1]);
                *(__half2*)&C[(size_t)m0 * N + n0] = v0;
                __half2 v1 = __floats2half2_rn(acc[mi][ni][2], acc[mi][ni][3]);
                *(__half2*)&C[(size_t)(m0 + 8) * N + n0] = v1;
            }
        }
    }
}

// ---- per-node attention logits (fp16 h, fp32 accum) -----------------------
__global__ void node_alpha_kernel(const __half* __restrict__ h,
                                  const float* __restrict__ a_s,
                                  const float* __restrict__ a_d,
                                  float* __restrict__ out_s,
                                  float* __restrict__ out_d,
                                  int H, int C) {
    int warp = (blockIdx.x * blockDim.x + threadIdx.x) >> 5;
    int lane = threadIdx.x & 31;
    if (warp >= NN * H) return;
    int n = warp / H;
    int hd = warp - n * H;
    const __half* hp = h + (size_t)n * H * C + (size_t)hd * C;
    const float* asv = a_s + (size_t)hd * C;
    const float* adv = a_d + (size_t)hd * C;
    float s = 0.f, d = 0.f;
    for (int cc = lane * 2; cc < C; cc += 64) {
        float2 v = __half22float2(*(const __half2*)&hp[cc]);
        s = fmaf(v.x, asv[cc], s);
        s = fmaf(v.y, asv[cc + 1], s);
        d = fmaf(v.x, adv[cc], d);
        d = fmaf(v.y, adv[cc + 1], d);
    }
    #pragma unroll
    for (int o = 16; o > 0; o >>= 1) {
        s += __shfl_xor_sync(0xffffffffu, s, o);
        d += __shfl_xor_sync(0xffffffffu, d, o);
    }
    if (lane == 0) {
        out_s[n * H + hd] = s;
        out_d[n * H + hd] = d;
    }
}

// ---- head-combined edge softmax -------------------------------------------
// warp per dst; all H heads per lane via float4. One gather pass; e staged
// in-place in alpha[], then exp+sum and normalize read it sequentially.
__device__ __forceinline__ float leaky(float x) {
    return x > 0.f ? x : NEG_SLOPE * x;
}

__global__ __launch_bounds__(256)
void edge_softmax4_kernel(const int* __restrict__ rowptr,
                          const int* __restrict__ csrsrc,
                          const float* __restrict__ as_,
                          const float* __restrict__ ad_,
                          float* __restrict__ alpha) {
    int d = (blockIdx.x * blockDim.x + threadIdx.x) >> 5;
    int lane = threadIdx.x & 31;
    if (d >= NN) return;
    int s0 = rowptr[d], s1 = rowptr[d + 1];
    float4 ad4 = *(const float4*)&ad_[d * 4];

    // pass 1: gather once, compute e, stage to alpha, track max
    float4 mx = make_float4(-3e38f, -3e38f, -3e38f, -3e38f);
    for (int p = s0 + lane; p < s1; p += 32) {
        int src = csrsrc[p];
        float4 g = *(const float4*)&as_[src * 4];
        float4 e;
        e.x = leaky(g.x + ad4.x);
        e.y = leaky(g.y + ad4.y);
        e.z = leaky(g.z + ad4.z);
        e.w = leaky(g.w + ad4.w);
        *(float4*)&alpha[(size_t)p * 4] = e;
        mx.x = fmaxf(mx.x, e.x); mx.y = fmaxf(mx.y, e.y);
        mx.z = fmaxf(mx.z, e.z); mx.w = fmaxf(mx.w, e.w);
    }
    #pragma unroll
    for (int o = 16; o > 0; o >>= 1) {
        mx.x = fmaxf(mx.x, __shfl_xor_sync(0xffffffffu, mx.x, o));
        mx.y = fmaxf(mx.y, __shfl_xor_sync(0xffffffffu, mx.y, o));
        mx.z = fmaxf(mx.z, __shfl_xor_sync(0xffffffffu, mx.z, o));
        mx.w = fmaxf(mx.w, __shfl_xor_sync(0xffffffffu, mx.w, o));
    }

    // pass 2: exp + sum (sequential reads)
    float4 sum = make_float4(0.f, 0.f, 0.f, 0.f);
    for (int p = s0 + lane; p < s1; p += 32) {
        float4 e = *(const float4*)&alpha[(size_t)p * 4];
        float4 ex;
        ex.x = expf(e.x - mx.x); ex.y = expf(e.y - mx.y);
        ex.z = expf(e.z - mx.z); ex.w = expf(e.w - mx.w);
        *(float4*)&alpha[(size_t)p * 4] = ex;
        sum.x += ex.x; sum.y += ex.y; sum.z += ex.z; sum.w += ex.w;
    }
    #pragma unroll
    for (int o = 16; o > 0; o >>= 1) {
        sum.x += __shfl_xor_sync(0xffffffffu, sum.x, o);
        sum.y += __shfl_xor_sync(0xffffffffu, sum.y, o);
        sum.z += __shfl_xor_sync(0xffffffffu, sum.z, o);
        sum.w += __shfl_xor_sync(0xffffffffu, sum.w, o);
    }
    float4 inv;
    inv.x = 1.f / sum.x; inv.y = 1.f / sum.y;
    inv.z = 1.f / sum.z; inv.w = 1.f / sum.w;

    // pass 3: normalize
    for (int p = s0 + lane; p < s1; p += 32) {
        float4 a = *(const float4*)&alpha[(size_t)p * 4];
        a.x *= inv.x; a.y *= inv.y; a.z *= inv.z; a.w *= inv.w;
        *(float4*)&alpha[(size_t)p * 4] = a;
    }
}

// H=1 variant (layer 4)
__global__ __launch_bounds__(256)
void edge_softmax1_kernel(const int* __restrict__ rowptr,
                          const int* __restrict__ csrsrc,
                          const float* __restrict__ as_,
                          const float* __restrict__ ad_,
                          float* __restrict__ alpha) {
    int d = (blockIdx.x * blockDim.x + threadIdx.x) >> 5;
    int lane = threadIdx.x & 31;
    if (d >= NN) return;
    int s0 = rowptr[d], s1 = rowptr[d + 1];
    float adv = ad_[d];

    float mx = -3e38f;
    for (int p = s0 + lane; p < s1; p += 32) {
        float e = leaky(as_[csrsrc[p]] + adv);
        alpha[p] = e;
        mx = fmaxf(mx, e);
    }
    #pragma unroll
    for (int o = 16; o > 0; o >>= 1)
        mx = fmaxf(mx, __shfl_xor_sync(0xffffffffu, mx, o));

    float sum = 0.f;
    for (int p = s0 + lane; p < s1; p += 32) {
        float ex = expf(alpha[p] - mx);
        alpha[p] = ex;
        sum += ex;
    }
    #pragma unroll
    for (int o = 16; o > 0; o >>= 1)
        sum += __shfl_xor_sync(0xffffffffu, sum, o);
    float inv = 1.f / sum;

    for (int p = s0 + lane; p < s1; p += 32)
        alpha[p] *= inv;
}

// ---- aggregation: out = relu(sum alpha*h16 + b) (round-6 version) ---------
template <bool F16OUT>
__global__ __launch_bounds__(256)
void aggregate_kernel(const __half* __restrict__ h,
                      const float* __restrict__ alpha,
                      const int* __restrict__ rowptr,
                      const int* __restrict__ csrsrc,
                      const float* __restrict__ bias,
                      float* __restrict__ out32,
                      __half* __restrict__ out16,
                      int H, int HC, int logC) {
    int d = blockIdx.x * blockDim.y + threadIdx.y;
    if (d >= NN) return;
    int f = threadIdx.x * 4;
    int head = f >> logC;

    float acc0 = 0.f, acc1 = 0.f, acc2 = 0.f, acc3 = 0.f;
    int s0 = rowptr[d], s1 = rowptr[d + 1];
    int p = s0;
    for (; p + 1 < s1; p += 2) {
        int srcA = csrsrc[p];
        int srcB = csrsrc[p + 1];
        float aA = alpha[(size_t)p * H + head];
        float aB = alpha[(size_t)(p + 1) * H + head];
        uint2 rA = *(const uint2*)&h[(size_t)srcA * HC + f];
        uint2 rB = *(const uint2*)&h[(size_t)srcB * HC + f];
        float2 vA0 = __half22float2(*(__half2*)&rA.x);
        float2 vA1 = __half22float2(*(__half2*)&rA.y);
        float2 vB0 = __half22float2(*(__half2*)&rB.x);
        float2 vB1 = __half22float2(*(__half2*)&rB.y);
        acc0 = fmaf(vA0.x, aA, fmaf(vB0.x, aB, acc0));
        acc1 = fmaf(vA0.y, aA, fmaf(vB0.y, aB, acc1));
        acc2 = fmaf(vA1.x, aA, fmaf(vB1.x, aB, acc2));
        acc3 = fmaf(vA1.y, aA, fmaf(vB1.y, aB, acc3));
    }
    if (p < s1) {
        int src = csrsrc[p];
        float a = alpha[(size_t)p * H + head];
        uint2 raw = *(const uint2*)&h[(size_t)src * HC + f];
        float2 v0 = __half22float2(*(__half2*)&raw.x);
        float2 v1 = __half22float2(*(__half2*)&raw.y);
        acc0 = fmaf(v0.x, a, acc0);
        acc1 = fmaf(v0.y, a, acc1);
        acc2 = fmaf(v1.x, a, acc2);
        acc3 = fmaf(v1.y, a, acc3);
    }

    float4 b = *(const float4*)&bias[f];
    float o0 = fmaxf(acc0 + b.x, 0.f);
    float o1 = fmaxf(acc1 + b.y, 0.f);
    float o2 = fmaxf(acc2 + b.z, 0.f);
    float o3 = fmaxf(acc3 + b.w, 0.f);
    if (F16OUT) {
        uint2 packed;
        *(__half2*)&packed.x = __floats2half2_rn(o0, o1);
        *(__half2*)&packed.y = __floats2half2_rn(o2, o3);
        *(uint2*)&out16[(size_t)d * HC + f] = packed;
    } else {
        float4 o = make_float4(o0, o1, o2, o3);
        *(float4*)&out32[(size_t)d * HC + f] = o;
    }
}

// ---------------------------------------------------------------------------
// host side
// ---------------------------------------------------------------------------
static inline void run_gemm(const __half* A, const __half* Bt, __half* C,
                            int N, int K) {
    dim3 grid((N + TBN - 1) / TBN, NPAD / TBM);
    h16gemm_kernel<<<grid, 256>>>(A, Bt, C, N, K);
}

static inline void run_aggregate(const __half* h, const float* alpha,
                                 const int* rowptr, const int* csrsrc,
                                 const float* bias, float* out32,
                                 __half* out16, int H, int HC, int logC) {
    int tx = HC / 4;
    int ty = 256 / tx;
    dim3 block(tx, ty);
    dim3 grid((NN + ty - 1) / ty);
    if (out16)
        aggregate_kernel<true><<<grid, block>>>(h, alpha, rowptr, csrsrc,
                                                bias, nullptr, out16, H, HC, logC);
    else
        aggregate_kernel<false><<<grid, block>>>(h, alpha, rowptr, csrsrc,
                                                 bias, out32, nullptr, H, HC, logC);
}

static inline void run_transpose(const float* W, __half* Wt, int K, int N) {
    dim3 grid((N + 31) / 32, (K + 31) / 32);
    transpose_w_kernel<<<grid, dim3(32, 8)>>>(W, Wt, K, N);
}

extern "C" void kernel_launch(void* const* d_in, const int* in_sizes, int n_in,
                              void* d_out, int out_size) {
    const float* x   = (const float*)d_in[0];
    const void*  ei  = d_in[1];
    const float* W1  = (const float*)d_in[2];
    const float* a1s = (const float*)d_in[3];
    const float* a1d = (const float*)d_in[4];
    const float* b1  = (const float*)d_in[5];
    const float* W2  = (const float*)d_in[6];
    const float* a2s = (const float*)d_in[7];
    const float* a2d = (const float*)d_in[8];
    const float* b2  = (const float*)d_in[9];
    const float* W3  = (const float*)d_in[10];
    const float* a3s = (const float*)d_in[11];
    const float* a3d = (const float*)d_in[12];
    const float* b3  = (const float*)d_in[13];
    const float* W4  = (const float*)d_in[14];
    const float* a4s = (const float*)d_in[15];
    const float* a4d = (const float*)d_in[16];
    const float* b4  = (const float*)d_in[17];
    float* out = (float*)d_out;

    float *asb, *adb, *alpha;
    __half *hA, *hB, *wt;
    int *deg, *rowptr, *cursor, *csrsrc, *is64;
    cudaGetSymbolAddress((void**)&hA, g_hA);
    cudaGetSymbolAddress((void**)&hB, g_hB);
    cudaGetSymbolAddress((void**)&wt, g_wt);
    cudaGetSymbolAddress((void**)&asb, g_as);
    cudaGetSymbolAddress((void**)&adb, g_ad);
    cudaGetSymbolAddress((void**)&alpha, g_alpha);
    cudaGetSymbolAddress((void**)&deg, g_deg);
    cudaGetSymbolAddress((void**)&rowptr, g_rowptr);
    cudaGetSymbolAddress((void**)&cursor, g_cursor);
    cudaGetSymbolAddress((void**)&csrsrc, g_csrsrc);
    cudaGetSymbolAddress((void**)&is64, g_is64);

    __half* wt1 = wt;                     // [512][256]
    __half* wt2 = wt + 131072;            // [512][512]
    __half* wt3 = wt + 131072 + 262144;   // [256][512]
    __half* wt4 = wt + 131072 + 262144 + 131072;  // [64][256]

    // ---- prep: CSR + dtype conversions ----
    cudaMemsetAsync(deg, 0, NN * sizeof(int));
    detect64_kernel<<<1, 32>>>((const int*)ei, is64);
    count_deg_kernel<<<(E_TOT + 255) / 256, 256>>>(ei, is64, deg);
    scan_kernel<<<1, 1024>>>(deg, rowptr, NN);
    cudaMemcpyAsync(cursor, rowptr, NN * sizeof(int), cudaMemcpyDeviceToDevice);
    fill_csr_kernel<<<(E_TOT + 255) / 256, 256>>>(ei, is64, cursor, csrsrc);

    f2h_kernel<<<(NN * 256 / 4 + 255) / 256, 256>>>(x, hA, NN * 256);
    run_transpose(W1, wt1, 256, 512);
    run_transpose(W2, wt2, 512, 512);
    run_transpose(W3, wt3, 512, 256);
    run_transpose(W4, wt4, 256, 64);

    auto nblocks_warps = [](int warps) { return (warps + 7) / 8; };

    // ---- layer 1: 256 -> 4x128 ----
    run_gemm(hA, wt1, hB, 512, 256);
    node_alpha_kernel<<<nblocks_warps(NN * 4), 256>>>(hB, a1s, a1d, asb, adb, 4, 128);
    edge_softmax4_kernel<<<nblocks_warps(NN), 256>>>(rowptr, csrsrc, asb, adb, alpha);
    run_aggregate(hB, alpha, rowptr, csrsrc, b1, nullptr, hA, 4, 512, 7);

    // ---- layer 2: 512 -> 4x128 ----
    run_gemm(hA, wt2, hB, 512, 512);
    node_alpha_kernel<<<nblocks_warps(NN * 4), 256>>>(hB, a2s, a2d, asb, adb, 4, 128);
    edge_softmax4_kernel<<<nblocks_warps(NN), 256>>>(rowptr, csrsrc, asb, adb, alpha);
    run_aggregate(hB, alpha, rowptr, csrsrc, b2, nullptr, hA, 4, 512, 7);

    // ---- layer 3: 512 -> 4x64 ----
    run_gemm(hA, wt3, hB, 256, 512);
    node_alpha_kernel<<<nblocks_warps(NN * 4), 256>>>(hB, a3s, a3d, asb, adb, 4, 64);
    edge_softmax4_kernel<<<nblocks_warps(NN), 256>>>(rowptr, csrsrc, asb, adb, alpha);
    run_aggregate(hB, alpha, rowptr, csrsrc, b3, nullptr, hA, 4, 256, 6);

    // ---- layer 4: 256 -> 1x64, concat=False ----
    run_gemm(hA, wt4, hB, 64, 256);
    node_alpha_kernel<<<nblocks_warps(NN * 1), 256>>>(hB, a4s, a4d, asb, adb, 1, 64);
    edge_softmax1_kernel<<<nblocks_warps(NN), 256>>>(rowptr, csrsrc, asb, adb, alpha);
    run_aggregate(hB, alpha, rowptr, csrsrc, b4, out, nullptr, 1, 64, 6);

    (void)in_sizes; (void)n_in; (void)out_size;
}

// round 9
// speedup vs baseline: 1.3130x; 1.1075x over previous
#include <cuda_runtime.h>
#include <cuda_fp16.h>
#include <cstdint>
#include <math.h>

// ---------------------------------------------------------------------------
// GAT 4-layer stack on GB300, round 9 (round-8 + 3 changes):
//  - attention logits fused into GEMM epilogue (node_alpha kernels deleted)
//  - aggregate: 4-edge unroll (more MLP)
//  - 4 weight transposes fused into one launch
// ---------------------------------------------------------------------------

#define NN      30000
#define NPAD    30080
#define E_RAW   480000
#define E_TOT   (E_RAW + NN)
#define MAXF    512
#define NEG_SLOPE 0.2f

// ---- scratch (device globals; zero-initialized at load) -------------------
__device__ __half g_hA[NPAD * MAXF];            // fp16 activations ping
__device__ __half g_hB[NPAD * MAXF];            // fp16 activations pong
__device__ __half g_wt[540672];                 // transposed fp16 weights
__device__ float  g_as[NN * 4];
__device__ float  g_ad[NN * 4];
__device__ float  g_alpha[(size_t)E_TOT * 4];
__device__ int    g_deg[NN];
__device__ int    g_rowptr[NN + 1];
__device__ int    g_cursor[NN];
__device__ int    g_csrsrc[E_TOT];
__device__ int    g_is64;

// ---------------------------------------------------------------------------
// edge_index dtype detection (int32 vs int64)
// ---------------------------------------------------------------------------
__global__ void detect64_kernel(const int* __restrict__ words, int* flag) {
    if (threadIdx.x == 0 && blockIdx.x == 0) {
        int any = 0;
        #pragma unroll 4
        for (int i = 0; i < 256; i++) any |= words[2 * i + 1];
        *flag = (any == 0) ? 1 : 0;
    }
}

__device__ __forceinline__ void get_edge(const void* ei, int e, int is64,
                                         int& src, int& dst) {
    if (e >= E_RAW) { src = dst = e - E_RAW; return; }
    if (is64) {
        const long long* p = (const long long*)ei;
        src = (int)p[e];
        dst = (int)p[E_RAW + e];
    } else {
        const int* p = (const int*)ei;
        src = p[e];
        dst = p[E_RAW + e];
    }
}

// ---- CSR build ------------------------------------------------------------
__global__ void count_deg_kernel(const void* __restrict__ ei,
                                 const int* __restrict__ flag,
                                 int* __restrict__ deg) {
    int e = blockIdx.x * blockDim.x + threadIdx.x;
    if (e >= E_TOT) return;
    int src, dst;
    get_edge(ei, e, *flag, src, dst);
    atomicAdd(&deg[dst], 1);
}

__global__ void scan_kernel(const int* __restrict__ deg,
                            int* __restrict__ rowptr, int n) {
    __shared__ int warpsums[32];
    __shared__ int carry_s;
    int t = threadIdx.x;
    int lane = t & 31;
    int w = t >> 5;
    if (t == 0) carry_s = 0;
    __syncthreads();
    for (int base = 0; base < n; base += 1024) {
        int i = base + t;
        int v = (i < n) ? deg[i] : 0;
        int x = v;
        #pragma unroll
        for (int o = 1; o < 32; o <<= 1) {
            int u = __shfl_up_sync(0xffffffffu, x, o);
            if (lane >= o) x += u;
        }
        if (lane == 31) warpsums[w] = x;
        __syncthreads();
        if (w == 0) {
            int s = warpsums[lane];
            #pragma unroll
            for (int o = 1; o < 32; o <<= 1) {
                int u = __shfl_up_sync(0xffffffffu, s, o);
                if (lane >= o) s += u;
            }
            warpsums[lane] = s;
        }
        __syncthreads();
        int woff = (w > 0) ? warpsums[w - 1] : 0;
        int incl = x + woff + carry_s;
        if (i < n) rowptr[i] = incl - v;
        __syncthreads();
        if (t == 1023) carry_s = incl;
        __syncthreads();
    }
    if (t == 0) rowptr[n] = carry_s;
}

__global__ void fill_csr_kernel(const void* __restrict__ ei,
                                const int* __restrict__ flag,
                                int* __restrict__ cursor,
                                int* __restrict__ csrsrc) {
    int e = blockIdx.x * blockDim.x + threadIdx.x;
    if (e >= E_TOT) return;
    int src, dst;
    get_edge(ei, e, *flag, src, dst);
    int pos = atomicAdd(&cursor[dst], 1);
    csrsrc[pos] = src;
}

// ---- prep: fp32 -> fp16 convert, fused weight transposes ------------------
__global__ void f2h_kernel(const float* __restrict__ in,
                           __half* __restrict__ out, int n) {
    int i = blockIdx.x * blockDim.x + threadIdx.x;
    int i4 = i * 4;
    if (i4 + 3 < n) {
        float4 v = *(const float4*)&in[i4];
        __half2 lo = __floats2half2_rn(v.x, v.y);
        __half2 hi = __floats2half2_rn(v.z, v.w);
        *(__half2*)&out[i4] = lo;
        *(__half2*)&out[i4 + 2] = hi;
    } else {
        for (int j = i4; j < n; j++) out[j] = __float2half_rn(in[j]);
    }
}

struct WtJob { const float* W; __half* Wt; int K, N; };

__global__ void transpose_all_kernel(WtJob j0, WtJob j1, WtJob j2, WtJob j3) {
    WtJob j = (blockIdx.z == 0) ? j0 : (blockIdx.z == 1) ? j1
            : (blockIdx.z == 2) ? j2 : j3;
    int k0 = blockIdx.y * 32, n0 = blockIdx.x * 32;
    if (k0 >= j.K || n0 >= j.N) return;
    __shared__ float tile[32][33];
    int tx = threadIdx.x, ty = threadIdx.y;
    for (int i = ty; i < 32; i += 8) {
        int k = k0 + i, n = n0 + tx;
        tile[i][tx] = (k < j.K && n < j.N) ? j.W[(size_t)k * j.N + n] : 0.f;
    }
    __syncthreads();
    for (int i = ty; i < 32; i += 8) {
        int n = n0 + i, k = k0 + tx;
        if (n < j.N && k < j.K)
            j.Wt[(size_t)n * j.K + k] = __float2half_rn(tile[tx][i]);
    }
}

// ---------------------------------------------------------------------------
// fp16 tensor-core GEMM + fused attention-logit epilogue.
// C16[M_pad x N] = A16 * Wt16^T; also out_s[n,h] = <h[n,h,:], a_s[h,:]>,
// out_d same. a_s flat([H][C]) == flat over columns, so s_av[j] = a_s[bn+j].
// Every (row, head) is contained in one CTA (C in {64,128} <= TBN, aligned).
// ---------------------------------------------------------------------------
#define TBM 128
#define TBN 128
#define TBK 32
#define SAH 40

__device__ __forceinline__ void cp16(unsigned int smem, const void* gptr, int sz) {
    asm volatile("cp.async.cg.shared.global [%0], [%1], 16, %2;\n"
                 :: "r"(smem), "l"(gptr), "r"(sz));
}

__device__ __forceinline__ unsigned int smem_u32(const void* p) {
    return (unsigned int)__cvta_generic_to_shared(p);
}

__device__ __forceinline__ void mma_f16(float* d, const unsigned* a,
                                        const unsigned* b) {
    asm volatile(
        "mma.sync.aligned.m16n8k16.row.col.f32.f16.f16.f32 "
        "{%0,%1,%2,%3}, {%4,%5,%6,%7}, {%8,%9}, {%0,%1,%2,%3};\n"
        : "+f"(d[0]), "+f"(d[1]), "+f"(d[2]), "+f"(d[3])
        : "r"(a[0]), "r"(a[1]), "r"(a[2]), "r"(a[3]),
          "r"(b[0]), "r"(b[1]));
}

__global__ __launch_bounds__(256, 2)
void h16gemm_kernel(const __half* __restrict__ A, const __half* __restrict__ Bt,
                    __half* __restrict__ C,
                    const float* __restrict__ a_s, const float* __restrict__ a_d,
                    float* __restrict__ out_s, float* __restrict__ out_d,
                    int N, int K, int H, int logC) {
    __shared__ __half As[2][TBM * SAH];
    __shared__ __half Bs[2][TBN * SAH];
    __shared__ float s_av[2][TBN];
    __shared__ float tmp_s[4][128];
    __shared__ float tmp_d[4][128];

    int tid  = threadIdx.x;
    int bm   = blockIdx.y * TBM;
    int bn   = blockIdx.x * TBN;
    int warp = tid >> 5;
    int lane = tid & 31;
    int wm   = (warp & 1) * 64;
    int wn   = (warp >> 1) * 32;
    int wnq  = warp >> 1;
    int r    = lane >> 2;
    int c    = lane & 3;

    float acc[4][4][4];
    #pragma unroll
    for (int mi = 0; mi < 4; mi++)
        #pragma unroll
        for (int ni = 0; ni < 4; ni++)
            #pragma unroll
            for (int q = 0; q < 4; q++) acc[mi][ni][q] = 0.f;

    int row0 = tid >> 1;
    int kc0  = (tid & 1) * 2;
    int niter = K / TBK;

    auto stage = [&](int buf, int k0) {
        #pragma unroll
        for (int j = 0; j < 2; j++) {
            int kc = kc0 + j;
            int smoff = (row0 * SAH + kc * 8) * 2;
            const __half* ga = A + (size_t)(bm + row0) * K + k0 + kc * 8;
            cp16(smem_u32(&As[buf][0]) + smoff, ga, 16);
            int rb = bn + row0;
            const __half* gb = Bt + (size_t)(rb < N ? rb : 0) * K + k0 + kc * 8;
            cp16(smem_u32(&Bs[buf][0]) + smoff, gb, rb < N ? 16 : 0);
        }
        asm volatile("cp.async.commit_group;\n");
    };

    stage(0, 0);

    for (int it = 0; it < niter; it++) {
        if (it + 1 < niter) {
            stage((it + 1) & 1, (it + 1) * TBK);
            asm volatile("cp.async.wait_group 1;\n");
        } else {
            asm volatile("cp.async.wait_group 0;\n");
        }
        __syncthreads();

        int buf = it & 1;
        #pragma unroll
        for (int kk = 0; kk < 2; kk++) {
            int kb = kk * 16;
            unsigned af[4][4];
            #pragma unroll
            for (int mi = 0; mi < 4; mi++) {
                const __half* ap = &As[buf][(wm + mi * 16 + r) * SAH + kb + 2 * c];
                af[mi][0] = *(const unsigned*)(ap);
                af[mi][1] = *(const unsigned*)(ap + 8 * SAH);
                af[mi][2] = *(const unsigned*)(ap + 8);
                af[mi][3] = *(const unsigned*)(ap + 8 * SAH + 8);
            }
            unsigned bf[4][2];
            #pragma unroll
            for (int ni = 0; ni < 4; ni++) {
                const __half* bp = &Bs[buf][(wn + ni * 8 + r) * SAH + kb + 2 * c];
                bf[ni][0] = *(const unsigned*)(bp);
                bf[ni][1] = *(const unsigned*)(bp + 8);
            }
            #pragma unroll
            for (int mi = 0; mi < 4; mi++)
                #pragma unroll
                for (int ni = 0; ni < 4; ni++)
                    mma_f16(acc[mi][ni], af[mi], bf[ni]);
        }
        __syncthreads();
    }

    // ---- store h (fp16) ----
    #pragma unroll
    for (int mi = 0; mi < 4; mi++) {
        int m0 = bm + wm + mi * 16 + r;
        #pragma unroll
        for (int ni = 0; ni < 4; ni++) {
            int n0 = bn + wn + ni * 8 + 2 * c;
            if (n0 < N) {
                __half2 v0 = __floats2half2_rn(acc[mi][ni][0], acc[mi][ni][1]);
                *(__half2*)&C[(size_t)m0 * N + n0] = v0;
                __half2 v1 = __floats2half2_rn(acc[mi][ni][2], acc[mi][ni][3]);
                *(__half2*)&C[(size_t)(m0 + 8) * N + n0] = v1;
            }
        }
    }

    // ---- fused logits: stage a vectors (flat [H][C] == per-column) ----
    if (tid < TBN) {
        int gcol = bn + tid;
        s_av[0][tid] = (gcol < N) ? a_s[gcol] : 0.f;
    } else {
        int gcol = bn + tid - TBN;
        s_av[1][tid - TBN] = (gcol < N) ? a_d[gcol] : 0.f;
    }
    __syncthreads();

    float ps[4][2], pd[4][2];
    #pragma unroll
    for (int mi = 0; mi < 4; mi++) {
        ps[mi][0] = ps[mi][1] = 0.f;
        pd[mi][0] = pd[mi][1] = 0.f;
    }
    #pragma unroll
    for (int mi = 0; mi < 4; mi++)
        #pragma unroll
        for (int ni = 0; ni < 4; ni++)
            #pragma unroll
            for (int q = 0; q < 4; q++) {
                int col = wn + ni * 8 + 2 * c + (q & 1);
                int hf = q >> 1;
                ps[mi][hf] = fmaf(acc[mi][ni][q], s_av[0][col], ps[mi][hf]);
                pd[mi][hf] = fmaf(acc[mi][ni][q], s_av[1][col], pd[mi][hf]);
            }
    // reduce over the 4 c-lanes; lane c==0 writes its 8 rows
    #pragma unroll
    for (int mi = 0; mi < 4; mi++)
        #pragma unroll
        for (int hf = 0; hf < 2; hf++) {
            float vs = ps[mi][hf], vd = pd[mi][hf];
            vs += __shfl_xor_sync(0xffffffffu, vs, 1);
            vs += __shfl_xor_sync(0xffffffffu, vs, 2);
            vd += __shfl_xor_sync(0xffffffffu, vd, 1);
            vd += __shfl_xor_sync(0xffffffffu, vd, 2);
            if (c == 0) {
                int row = wm + mi * 16 + r + hf * 8;
                tmp_s[wnq][row] = vs;
                tmp_d[wnq][row] = vd;
            }
        }
    __syncthreads();

    int hpb = TBN >> logC;        // heads per block: 1 (C=128) or 2 (C=64)
    int gph = 4 / hpb;            // wn-groups per head
    if (tid < 128) {
        int row = tid, n = bm + row;
        if (n < NN) {
            for (int hl = 0; hl < hpb; hl++) {
                int colbase = hl << logC;
                if (bn + colbase < N) {
                    float sum = 0.f;
                    for (int g = 0; g < gph; g++) sum += tmp_s[hl * gph + g][row];
                    int head = (bn + colbase) >> logC;
                    out_s[n * H + head] = sum;
                }
            }
        }
    } else {
        int row = tid - 128, n = bm + row;
        if (n < NN) {
            for (int hl = 0; hl < hpb; hl++) {
                int colbase = hl << logC;
                if (bn + colbase < N) {
                    float sum = 0.f;
                    for (int g = 0; g < gph; g++) sum += tmp_d[hl * gph + g][row];
                    int head = (bn + colbase) >> logC;
                    out_d[n * H + head] = sum;
                }
            }
        }
    }
}

// ---- head-combined edge softmax -------------------------------------------
__device__ __forceinline__ float leaky(float x) {
    return x > 0.f ? x : NEG_SLOPE * x;
}

__global__ __launch_bounds__(256)
void edge_softmax4_kernel(const int* __restrict__ rowptr,
                          const int* __restrict__ csrsrc,
                          const float* __restrict__ as_,
                          const float* __restrict__ ad_,
                          float* __restrict__ alpha) {
    int d = (blockIdx.x * blockDim.x + threadIdx.x) >> 5;
    int lane = threadIdx.x & 31;
    if (d >= NN) return;
    int s0 = rowptr[d], s1 = rowptr[d + 1];
    float4 ad4 = *(const float4*)&ad_[d * 4];

    float4 mx = make_float4(-3e38f, -3e38f, -3e38f, -3e38f);
    for (int p = s0 + lane; p < s1; p += 32) {
        int src = csrsrc[p];
        float4 g = *(const float4*)&as_[src * 4];
        float4 e;
        e.x = leaky(g.x + ad4.x);
        e.y = leaky(g.y + ad4.y);
        e.z = leaky(g.z + ad4.z);
        e.w = leaky(g.w + ad4.w);
        *(float4*)&alpha[(size_t)p * 4] = e;
        mx.x = fmaxf(mx.x, e.x); mx.y = fmaxf(mx.y, e.y);
        mx.z = fmaxf(mx.z, e.z); mx.w = fmaxf(mx.w, e.w);
    }
    #pragma unroll
    for (int o = 16; o > 0; o >>= 1) {
        mx.x = fmaxf(mx.x, __shfl_xor_sync(0xffffffffu, mx.x, o));
        mx.y = fmaxf(mx.y, __shfl_xor_sync(0xffffffffu, mx.y, o));
        mx.z = fmaxf(mx.z, __shfl_xor_sync(0xffffffffu, mx.z, o));
        mx.w = fmaxf(mx.w, __shfl_xor_sync(0xffffffffu, mx.w, o));
    }

    float4 sum = make_float4(0.f, 0.f, 0.f, 0.f);
    for (int p = s0 + lane; p < s1; p += 32) {
        float4 e = *(const float4*)&alpha[(size_t)p * 4];
        float4 ex;
        ex.x = expf(e.x - mx.x); ex.y = expf(e.y - mx.y);
        ex.z = expf(e.z - mx.z); ex.w = expf(e.w - mx.w);
        *(float4*)&alpha[(size_t)p * 4] = ex;
        sum.x += ex.x; sum.y += ex.y; sum.z += ex.z; sum.w += ex.w;
    }
    #pragma unroll
    for (int o = 16; o > 0; o >>= 1) {
        sum.x += __shfl_xor_sync(0xffffffffu, sum.x, o);
        sum.y += __shfl_xor_sync(0xffffffffu, sum.y, o);
        sum.z += __shfl_xor_sync(0xffffffffu, sum.z, o);
        sum.w += __shfl_xor_sync(0xffffffffu, sum.w, o);
    }
    float4 inv;
    inv.x = 1.f / sum.x; inv.y = 1.f / sum.y;
    inv.z = 1.f / sum.z; inv.w = 1.f / sum.w;

    for (int p = s0 + lane; p < s1; p += 32) {
        float4 a = *(const float4*)&alpha[(size_t)p * 4];
        a.x *= inv.x; a.y *= inv.y; a.z *= inv.z; a.w *= inv.w;
        *(float4*)&alpha[(size_t)p * 4] = a;
    }
}

__global__ __launch_bounds__(256)
void edge_softmax1_kernel(const int* __restrict__ rowptr,
                          const int* __restrict__ csrsrc,
                          const float* __restrict__ as_,
                          const float* __restrict__ ad_,
                          float* __restrict__ alpha) {
    int d = (blockIdx.x * blockDim.x + threadIdx.x) >> 5;
    int lane = threadIdx.x & 31;
    if (d >= NN) return;
    int s0 = rowptr[d], s1 = rowptr[d + 1];
    float adv = ad_[d];

    float mx = -3e38f;
    for (int p = s0 + lane; p < s1; p += 32) {
        float e = leaky(as_[csrsrc[p]] + adv);
        alpha[p] = e;
        mx = fmaxf(mx, e);
    }
    #pragma unroll
    for (int o = 16; o > 0; o >>= 1)
        mx = fmaxf(mx, __shfl_xor_sync(0xffffffffu, mx, o));

    float sum = 0.f;
    for (int p = s0 + lane; p < s1; p += 32) {
        float ex = expf(alpha[p] - mx);
        alpha[p] = ex;
        sum += ex;
    }
    #pragma unroll
    for (int o = 16; o > 0; o >>= 1)
        sum += __shfl_xor_sync(0xffffffffu, sum, o);
    float inv = 1.f / sum;

    for (int p = s0 + lane; p < s1; p += 32)
        alpha[p] *= inv;
}

// ---- aggregation: out = relu(sum alpha*h16 + b); 4-edge unroll ------------
template <bool F16OUT>
__global__ __launch_bounds__(256)
void aggregate_kernel(const __half* __restrict__ h,
                      const float* __restrict__ alpha,
                      const int* __restrict__ rowptr,
                      const int* __restrict__ csrsrc,
                      const float* __restrict__ bias,
                      float* __restrict__ out32,
                      __half* __restrict__ out16,
                      int H, int HC, int logC) {
    int d = blockIdx.x * blockDim.y + threadIdx.y;
    if (d >= NN) return;
    int f = threadIdx.x * 4;
    int head = f >> logC;

    float acc0 = 0.f, acc1 = 0.f, acc2 = 0.f, acc3 = 0.f;
    int s0 = rowptr[d], s1 = rowptr[d + 1];
    int p = s0;
    for (; p + 3 < s1; p += 4) {
        int sA = csrsrc[p],     sB = csrsrc[p + 1];
        int sC = csrsrc[p + 2], sD = csrsrc[p + 3];
        float aA = alpha[(size_t)p * H + head];
        float aB = alpha[(size_t)(p + 1) * H + head];
        float aC = alpha[(size_t)(p + 2) * H + head];
        float aD = alpha[(size_t)(p + 3) * H + head];
        uint2 rA = *(const uint2*)&h[(size_t)sA * HC + f];
        uint2 rB = *(const uint2*)&h[(size_t)sB * HC + f];
        uint2 rC = *(const uint2*)&h[(size_t)sC * HC + f];
        uint2 rD = *(const uint2*)&h[(size_t)sD * HC + f];
        float2 vA0 = __half22float2(*(__half2*)&rA.x);
        float2 vA1 = __half22float2(*(__half2*)&rA.y);
        float2 vB0 = __half22float2(*(__half2*)&rB.x);
        float2 vB1 = __half22float2(*(__half2*)&rB.y);
        float2 vC0 = __half22float2(*(__half2*)&rC.x);
        float2 vC1 = __half22float2(*(__half2*)&rC.y);
        float2 vD0 = __half22float2(*(__half2*)&rD.x);
        float2 vD1 = __half22float2(*(__half2*)&rD.y);
        acc0 = fmaf(vA0.x, aA, fmaf(vB0.x, aB, fmaf(vC0.x, aC, fmaf(vD0.x, aD, acc0))));
        acc1 = fmaf(vA0.y, aA, fmaf(vB0.y, aB, fmaf(vC0.y, aC, fmaf(vD0.y, aD, acc1))));
        acc2 = fmaf(vA1.x, aA, fmaf(vB1.x, aB, fmaf(vC1.x, aC, fmaf(vD1.x, aD, acc2))));
        acc3 = fmaf(vA1.y, aA, fmaf(vB1.y, aB, fmaf(vC1.y, aC, fmaf(vD1.y, aD, acc3))));
    }
    for (; p < s1; p++) {
        int src = csrsrc[p];
        float a = alpha[(size_t)p * H + head];
        uint2 raw = *(const uint2*)&h[(size_t)src * HC + f];
        float2 v0 = __half22float2(*(__half2*)&raw.x);
        float2 v1 = __half22float2(*(__half2*)&raw.y);
        acc0 = fmaf(v0.x, a, acc0);
        acc1 = fmaf(v0.y, a, acc1);
        acc2 = fmaf(v1.x, a, acc2);
        acc3 = fmaf(v1.y, a, acc3);
    }

    float4 b = *(const float4*)&bias[f];
    float o0 = fmaxf(acc0 + b.x, 0.f);
    float o1 = fmaxf(acc1 + b.y, 0.f);
    float o2 = fmaxf(acc2 + b.z, 0.f);
    float o3 = fmaxf(acc3 + b.w, 0.f);
    if (F16OUT) {
        uint2 packed;
        *(__half2*)&packed.x = __floats2half2_rn(o0, o1);
        *(__half2*)&packed.y = __floats2half2_rn(o2, o3);
        *(uint2*)&out16[(size_t)d * HC + f] = packed;
    } else {
        float4 o = make_float4(o0, o1, o2, o3);
        *(float4*)&out32[(size_t)d * HC + f] = o;
    }
}

// ---------------------------------------------------------------------------
// host side
// ---------------------------------------------------------------------------
static inline void run_gemm(const __half* A, const __half* Bt, __half* C,
                            const float* a_s, const float* a_d,
                            float* out_s, float* out_d,
                            int N, int K, int H, int logC) {
    dim3 grid((N + TBN - 1) / TBN, NPAD / TBM);
    h16gemm_kernel<<<grid, 256>>>(A, Bt, C, a_s, a_d, out_s, out_d,
                                  N, K, H, logC);
}

static inline void run_aggregate(const __half* h, const float* alpha,
                                 const int* rowptr, const int* csrsrc,
                                 const float* bias, float* out32,
                                 __half* out16, int H, int HC, int logC) {
    int tx = HC / 4;
    int ty = 256 / tx;
    dim3 block(tx, ty);
    dim3 grid((NN + ty - 1) / ty);
    if (out16)
        aggregate_kernel<true><<<grid, block>>>(h, alpha, rowptr, csrsrc,
                                                bias, nullptr, out16, H, HC, logC);
    else
        aggregate_kernel<false><<<grid, block>>>(h, alpha, rowptr, csrsrc,
                                                 bias, out32, nullptr, H, HC, logC);
}

extern "C" void kernel_launch(void* const* d_in, const int* in_sizes, int n_in,
                              void* d_out, int out_size) {
    const float* x   = (const float*)d_in[0];
    const void*  ei  = d_in[1];
    const float* W1  = (const float*)d_in[2];
    const float* a1s = (const float*)d_in[3];
    const float* a1d = (const float*)d_in[4];
    const float* b1  = (const float*)d_in[5];
    const float* W2  = (const float*)d_in[6];
    const float* a2s = (const float*)d_in[7];
    const float* a2d = (const float*)d_in[8];
    const float* b2  = (const float*)d_in[9];
    const float* W3  = (const float*)d_in[10];
    const float* a3s = (const float*)d_in[11];
    const float* a3d = (const float*)d_in[12];
    const float* b3  = (const float*)d_in[13];
    const float* W4  = (const float*)d_in[14];
    const float* a4s = (const float*)d_in[15];
    const float* a4d = (const float*)d_in[16];
    const float* b4  = (const float*)d_in[17];
    float* out = (float*)d_out;

    float *asb, *adb, *alpha;
    __half *hA, *hB, *wt;
    int *deg, *rowptr, *cursor, *csrsrc, *is64;
    cudaGetSymbolAddress((void**)&hA, g_hA);
    cudaGetSymbolAddress((void**)&hB, g_hB);
    cudaGetSymbolAddress((void**)&wt, g_wt);
    cudaGetSymbolAddress((void**)&asb, g_as);
    cudaGetSymbolAddress((void**)&adb, g_ad);
    cudaGetSymbolAddress((void**)&alpha, g_alpha);
    cudaGetSymbolAddress((void**)&deg, g_deg);
    cudaGetSymbolAddress((void**)&rowptr, g_rowptr);
    cudaGetSymbolAddress((void**)&cursor, g_cursor);
    cudaGetSymbolAddress((void**)&csrsrc, g_csrsrc);
    cudaGetSymbolAddress((void**)&is64, g_is64);

    __half* wt1 = wt;                     // [512][256]
    __half* wt2 = wt + 131072;            // [512][512]
    __half* wt3 = wt + 131072 + 262144;   // [256][512]
    __half* wt4 = wt + 131072 + 262144 + 131072;  // [64][256]

    // ---- prep: CSR + dtype conversions ----
    cudaMemsetAsync(deg, 0, NN * sizeof(int));
    detect64_kernel<<<1, 32>>>((const int*)ei, is64);
    count_deg_kernel<<<(E_TOT + 255) / 256, 256>>>(ei, is64, deg);
    scan_kernel<<<1, 1024>>>(deg, rowptr, NN);
    cudaMemcpyAsync(cursor, rowptr, NN * sizeof(int), cudaMemcpyDeviceToDevice);
    fill_csr_kernel<<<(E_TOT + 255) / 256, 256>>>(ei, is64, cursor, csrsrc);

    f2h_kernel<<<(NN * 256 / 4 + 255) / 256, 256>>>(x, hA, NN * 256);
    {
        WtJob j1{W1, wt1, 256, 512};
        WtJob j2{W2, wt2, 512, 512};
        WtJob j3{W3, wt3, 512, 256};
        WtJob j4{W4, wt4, 256, 64};
        transpose_all_kernel<<<dim3(16, 16, 4), dim3(32, 8)>>>(j1, j2, j3, j4);
    }

    auto nblocks_warps = [](int warps) { return (warps + 7) / 8; };

    // ---- layer 1: 256 -> 4x128 ----
    run_gemm(hA, wt1, hB, a1s, a1d, asb, adb, 512, 256, 4, 7);
    edge_softmax4_kernel<<<nblocks_warps(NN), 256>>>(rowptr, csrsrc, asb, adb, alpha);
    run_aggregate(hB, alpha, rowptr, csrsrc, b1, nullptr, hA, 4, 512, 7);

    // ---- layer 2: 512 -> 4x128 ----
    run_gemm(hA, wt2, hB, a2s, a2d, asb, adb, 512, 512, 4, 7);
    edge_softmax4_kernel<<<nblocks_warps(NN), 256>>>(rowptr, csrsrc, asb, adb, alpha);
    run_aggregate(hB, alpha, rowptr, csrsrc, b2, nullptr, hA, 4, 512, 7);

    // ---- layer 3: 512 -> 4x64 ----
    run_gemm(hA, wt3, hB, a3s, a3d, asb, adb, 256, 512, 4, 6);
    edge_softmax4_kernel<<<nblocks_warps(NN), 256>>>(rowptr, csrsrc, asb, adb, alpha);
    run_aggregate(hB, alpha, rowptr, csrsrc, b3, nullptr, hA, 4, 256, 6);

    // ---- layer 4: 256 -> 1x64, concat=False ----
    run_gemm(hA, wt4, hB, a4s, a4d, asb, adb, 64, 256, 1, 6);
    edge_softmax1_kernel<<<nblocks_warps(NN), 256>>>(rowptr, csrsrc, asb, adb, alpha);
    run_aggregate(hB, alpha, rowptr, csrsrc, b4, out, nullptr, 1, 64, 6);

    (void)in_sizes; (void)n_in; (void)out_size;
}

// round 10
// speedup vs baseline: 1.3725x; 1.0453x over previous
#include <cuda_runtime.h>
#include <cuda_fp16.h>
#include <cstdint>
#include <math.h>

// ---------------------------------------------------------------------------
// GAT 4-layer stack on GB300, round 10 (round-9 + 2 changes):
//  - GEMM: 3-stage cp.async pipeline (prefetch depth 2, 1 barrier/iter),
//    dynamic smem (epilogue temporaries alias stage buffers)
//  - softmax normalize folded into aggregate (pass 3 deleted, inv table)
// ---------------------------------------------------------------------------

#define NN      30000
#define NPAD    30080
#define E_RAW   480000
#define E_TOT   (E_RAW + NN)
#define MAXF    512
#define NEG_SLOPE 0.2f

// ---- scratch (device globals; zero-initialized at load) -------------------
__device__ __half g_hA[NPAD * MAXF];            // fp16 activations ping
__device__ __half g_hB[NPAD * MAXF];            // fp16 activations pong
__device__ __half g_wt[540672];                 // transposed fp16 weights
__device__ float  g_as[NN * 4];
__device__ float  g_ad[NN * 4];
__device__ float  g_inv[NN * 4];                // 1/den per (dst,head)
__device__ float  g_alpha[(size_t)E_TOT * 4];   // unnormalized exp weights
__device__ int    g_deg[NN];
__device__ int    g_rowptr[NN + 1];
__device__ int    g_cursor[NN];
__device__ int    g_csrsrc[E_TOT];
__device__ int    g_is64;

// ---------------------------------------------------------------------------
// edge_index dtype detection (int32 vs int64)
// ---------------------------------------------------------------------------
__global__ void detect64_kernel(const int* __restrict__ words, int* flag) {
    if (threadIdx.x == 0 && blockIdx.x == 0) {
        int any = 0;
        #pragma unroll 4
        for (int i = 0; i < 256; i++) any |= words[2 * i + 1];
        *flag = (any == 0) ? 1 : 0;
    }
}

__device__ __forceinline__ void get_edge(const void* ei, int e, int is64,
                                         int& src, int& dst) {
    if (e >= E_RAW) { src = dst = e - E_RAW; return; }
    if (is64) {
        const long long* p = (const long long*)ei;
        src = (int)p[e];
        dst = (int)p[E_RAW + e];
    } else {
        const int* p = (const int*)ei;
        src = p[e];
        dst = p[E_RAW + e];
    }
}

// ---- CSR build ------------------------------------------------------------
__global__ void count_deg_kernel(const void* __restrict__ ei,
                                 const int* __restrict__ flag,
                                 int* __restrict__ deg) {
    int e = blockIdx.x * blockDim.x + threadIdx.x;
    if (e >= E_TOT) return;
    int src, dst;
    get_edge(ei, e, *flag, src, dst);
    atomicAdd(&deg[dst], 1);
}

__global__ void scan_kernel(const int* __restrict__ deg,
                            int* __restrict__ rowptr, int n) {
    __shared__ int warpsums[32];
    __shared__ int carry_s;
    int t = threadIdx.x;
    int lane = t & 31;
    int w = t >> 5;
    if (t == 0) carry_s = 0;
    __syncthreads();
    for (int base = 0; base < n; base += 1024) {
        int i = base + t;
        int v = (i < n) ? deg[i] : 0;
        int x = v;
        #pragma unroll
        for (int o = 1; o < 32; o <<= 1) {
            int u = __shfl_up_sync(0xffffffffu, x, o);
            if (lane >= o) x += u;
        }
        if (lane == 31) warpsums[w] = x;
        __syncthreads();
        if (w == 0) {
            int s = warpsums[lane];
            #pragma unroll
            for (int o = 1; o < 32; o <<= 1) {
                int u = __shfl_up_sync(0xffffffffu, s, o);
                if (lane >= o) s += u;
            }
            warpsums[lane] = s;
        }
        __syncthreads();
        int woff = (w > 0) ? warpsums[w - 1] : 0;
        int incl = x + woff + carry_s;
        if (i < n) rowptr[i] = incl - v;
        __syncthreads();
        if (t == 1023) carry_s = incl;
        __syncthreads();
    }
    if (t == 0) rowptr[n] = carry_s;
}

__global__ void fill_csr_kernel(const void* __restrict__ ei,
                                const int* __restrict__ flag,
                                int* __restrict__ cursor,
                                int* __restrict__ csrsrc) {
    int e = blockIdx.x * blockDim.x + threadIdx.x;
    if (e >= E_TOT) return;
    int src, dst;
    get_edge(ei, e, *flag, src, dst);
    int pos = atomicAdd(&cursor[dst], 1);
    csrsrc[pos] = src;
}

// ---- prep: fp32 -> fp16 convert, fused weight transposes ------------------
__global__ void f2h_kernel(const float* __restrict__ in,
                           __half* __restrict__ out, int n) {
    int i = blockIdx.x * blockDim.x + threadIdx.x;
    int i4 = i * 4;
    if (i4 + 3 < n) {
        float4 v = *(const float4*)&in[i4];
        __half2 lo = __floats2half2_rn(v.x, v.y);
        __half2 hi = __floats2half2_rn(v.z, v.w);
        *(__half2*)&out[i4] = lo;
        *(__half2*)&out[i4 + 2] = hi;
    } else {
        for (int j = i4; j < n; j++) out[j] = __float2half_rn(in[j]);
    }
}

struct WtJob { const float* W; __half* Wt; int K, N; };

__global__ void transpose_all_kernel(WtJob j0, WtJob j1, WtJob j2, WtJob j3) {
    WtJob j = (blockIdx.z == 0) ? j0 : (blockIdx.z == 1) ? j1
            : (blockIdx.z == 2) ? j2 : j3;
    int k0 = blockIdx.y * 32, n0 = blockIdx.x * 32;
    if (k0 >= j.K || n0 >= j.N) return;
    __shared__ float tile[32][33];
    int tx = threadIdx.x, ty = threadIdx.y;
    for (int i = ty; i < 32; i += 8) {
        int k = k0 + i, n = n0 + tx;
        tile[i][tx] = (k < j.K && n < j.N) ? j.W[(size_t)k * j.N + n] : 0.f;
    }
    __syncthreads();
    for (int i = ty; i < 32; i += 8) {
        int n = n0 + i, k = k0 + tx;
        if (n < j.N && k < j.K)
            j.Wt[(size_t)n * j.K + k] = __float2half_rn(tile[tx][i]);
    }
}

// ---------------------------------------------------------------------------
// fp16 tensor-core GEMM + fused attention-logit epilogue.
// 3-stage cp.async pipeline, dynamic smem.
// ---------------------------------------------------------------------------
#define TBM 128
#define TBN 128
#define TBK 32
#define SAH 40
#define GEMM_SMEM (3 * (TBM + TBN) * SAH * 2)   // 61440 bytes

__device__ __forceinline__ void cp16(unsigned int smem, const void* gptr, int sz) {
    asm volatile("cp.async.cg.shared.global [%0], [%1], 16, %2;\n"
                 :: "r"(smem), "l"(gptr), "r"(sz));
}

__device__ __forceinline__ unsigned int smem_u32(const void* p) {
    return (unsigned int)__cvta_generic_to_shared(p);
}

__device__ __forceinline__ void mma_f16(float* d, const unsigned* a,
                                        const unsigned* b) {
    asm volatile(
        "mma.sync.aligned.m16n8k16.row.col.f32.f16.f16.f32 "
        "{%0,%1,%2,%3}, {%4,%5,%6,%7}, {%8,%9}, {%0,%1,%2,%3};\n"
        : "+f"(d[0]), "+f"(d[1]), "+f"(d[2]), "+f"(d[3])
        : "r"(a[0]), "r"(a[1]), "r"(a[2]), "r"(a[3]),
          "r"(b[0]), "r"(b[1]));
}

__global__ __launch_bounds__(256, 2)
void h16gemm_kernel(const __half* __restrict__ A, const __half* __restrict__ Bt,
                    __half* __restrict__ C,
                    const float* __restrict__ a_s, const float* __restrict__ a_d,
                    float* __restrict__ out_s, float* __restrict__ out_d,
                    int N, int K, int H, int logC) {
    extern __shared__ __align__(16) char dsm[];
    __half* As = (__half*)dsm;                  // [3][TBM*SAH]
    __half* Bs = As + 3 * TBM * SAH;            // [3][TBN*SAH]
    // epilogue temporaries alias the stage buffers (used after mainloop only)
    float* s_av  = (float*)dsm;                 // [2][TBN]
    float* tmp_s = s_av + 2 * TBN;              // [4][128]
    float* tmp_d = tmp_s + 4 * 128;             // [4][128]

    int tid  = threadIdx.x;
    int bm   = blockIdx.y * TBM;
    int bn   = blockIdx.x * TBN;
    int warp = tid >> 5;
    int lane = tid & 31;
    int wm   = (warp & 1) * 64;
    int wn   = (warp >> 1) * 32;
    int wnq  = warp >> 1;
    int r    = lane >> 2;
    int c    = lane & 3;

    float acc[4][4][4];
    #pragma unroll
    for (int mi = 0; mi < 4; mi++)
        #pragma unroll
        for (int ni = 0; ni < 4; ni++)
            #pragma unroll
            for (int q = 0; q < 4; q++) acc[mi][ni][q] = 0.f;

    int row0 = tid >> 1;
    int kc0  = (tid & 1) * 2;
    int niter = K / TBK;

    auto stage = [&](int buf, int k0) {
        #pragma unroll
        for (int j = 0; j < 2; j++) {
            int kc = kc0 + j;
            int smoff = (row0 * SAH + kc * 8) * 2;
            const __half* ga = A + (size_t)(bm + row0) * K + k0 + kc * 8;
            cp16(smem_u32(&As[buf * TBM * SAH]) + smoff, ga, 16);
            int rb = bn + row0;
            const __half* gb = Bt + (size_t)(rb < N ? rb : 0) * K + k0 + kc * 8;
            cp16(smem_u32(&Bs[buf * TBN * SAH]) + smoff, gb, rb < N ? 16 : 0);
        }
        asm volatile("cp.async.commit_group;\n");
    };

    stage(0, 0);
    stage(1, TBK);

    for (int it = 0; it < niter; it++) {
        if (it < niter - 1) {
            asm volatile("cp.async.wait_group 1;\n");
        } else {
            asm volatile("cp.async.wait_group 0;\n");
        }
        __syncthreads();
        if (it + 2 < niter) stage((it + 2) % 3, (it + 2) * TBK);

        int buf = it % 3;
        const __half* Ab = &As[buf * TBM * SAH];
        const __half* Bb = &Bs[buf * TBN * SAH];
        #pragma unroll
        for (int kk = 0; kk < 2; kk++) {
            int kb = kk * 16;
            unsigned af[4][4];
            #pragma unroll
            for (int mi = 0; mi < 4; mi++) {
                const __half* ap = &Ab[(wm + mi * 16 + r) * SAH + kb + 2 * c];
                af[mi][0] = *(const unsigned*)(ap);
                af[mi][1] = *(const unsigned*)(ap + 8 * SAH);
                af[mi][2] = *(const unsigned*)(ap + 8);
                af[mi][3] = *(const unsigned*)(ap + 8 * SAH + 8);
            }
            unsigned bf[4][2];
            #pragma unroll
            for (int ni = 0; ni < 4; ni++) {
                const __half* bp = &Bb[(wn + ni * 8 + r) * SAH + kb + 2 * c];
                bf[ni][0] = *(const unsigned*)(bp);
                bf[ni][1] = *(const unsigned*)(bp + 8);
            }
            #pragma unroll
            for (int mi = 0; mi < 4; mi++)
                #pragma unroll
                for (int ni = 0; ni < 4; ni++)
                    mma_f16(acc[mi][ni], af[mi], bf[ni]);
        }
    }
    __syncthreads();   // all compute done before epilogue aliases smem

    // ---- store h (fp16) ----
    #pragma unroll
    for (int mi = 0; mi < 4; mi++) {
        int m0 = bm + wm + mi * 16 + r;
        #pragma unroll
        for (int ni = 0; ni < 4; ni++) {
            int n0 = bn + wn + ni * 8 + 2 * c;
            if (n0 < N) {
                __half2 v0 = __floats2half2_rn(acc[mi][ni][0], acc[mi][ni][1]);
                *(__half2*)&C[(size_t)m0 * N + n0] = v0;
                __half2 v1 = __floats2half2_rn(acc[mi][ni][2], acc[mi][ni][3]);
                *(__half2*)&C[(size_t)(m0 + 8) * N + n0] = v1;
            }
        }
    }

    // ---- fused logits: stage a vectors (flat [H][C] == per-column) ----
    if (tid < TBN) {
        int gcol = bn + tid;
        s_av[tid] = (gcol < N) ? a_s[gcol] : 0.f;
    } else {
        int gcol = bn + tid - TBN;
        s_av[TBN + tid - TBN] = (gcol < N) ? a_d[gcol] : 0.f;
    }
    __syncthreads();

    float ps[4][2], pd[4][2];
    #pragma unroll
    for (int mi = 0; mi < 4; mi++) {
        ps[mi][0] = ps[mi][1] = 0.f;
        pd[mi][0] = pd[mi][1] = 0.f;
    }
    #pragma unroll
    for (int mi = 0; mi < 4; mi++)
        #pragma unroll
        for (int ni = 0; ni < 4; ni++)
            #pragma unroll
            for (int q = 0; q < 4; q++) {
                int col = wn + ni * 8 + 2 * c + (q & 1);
                int hf = q >> 1;
                ps[mi][hf] = fmaf(acc[mi][ni][q], s_av[col], ps[mi][hf]);
                pd[mi][hf] = fmaf(acc[mi][ni][q], s_av[TBN + col], pd[mi][hf]);
            }
    #pragma unroll
    for (int mi = 0; mi < 4; mi++)
        #pragma unroll
        for (int hf = 0; hf < 2; hf++) {
            float vs = ps[mi][hf], vd = pd[mi][hf];
            vs += __shfl_xor_sync(0xffffffffu, vs, 1);
            vs += __shfl_xor_sync(0xffffffffu, vs, 2);
            vd += __shfl_xor_sync(0xffffffffu, vd, 1);
            vd += __shfl_xor_sync(0xffffffffu, vd, 2);
            if (c == 0) {
                int row = wm + mi * 16 + r + hf * 8;
                tmp_s[wnq * 128 + row] = vs;
                tmp_d[wnq * 128 + row] = vd;
            }
        }
    __syncthreads();

    int hpb = TBN >> logC;        // heads per block: 1 (C=128) or 2 (C=64)
    int gph = 4 / hpb;            // wn-groups per head
    if (tid < 128) {
        int row = tid, n = bm + row;
        if (n < NN) {
            for (int hl = 0; hl < hpb; hl++) {
                int colbase = hl << logC;
                if (bn + colbase < N) {
                    float sum = 0.f;
                    for (int g = 0; g < gph; g++)
                        sum += tmp_s[(hl * gph + g) * 128 + row];
                    int head = (bn + colbase) >> logC;
                    out_s[n * H + head] = sum;
                }
            }
        }
    } else {
        int row = tid - 128, n = bm + row;
        if (n < NN) {
            for (int hl = 0; hl < hpb; hl++) {
                int colbase = hl << logC;
                if (bn + colbase < N) {
                    float sum = 0.f;
                    for (int g = 0; g < gph; g++)
                        sum += tmp_d[(hl * gph + g) * 128 + row];
                    int head = (bn + colbase) >> logC;
                    out_d[n * H + head] = sum;
                }
            }
        }
    }
}

// ---- head-combined edge softmax (2 passes; inv stored, no normalize) ------
__device__ __forceinline__ float leaky(float x) {
    return x > 0.f ? x : NEG_SLOPE * x;
}

__global__ __launch_bounds__(256)
void edge_softmax4_kernel(const int* __restrict__ rowptr,
                          const int* __restrict__ csrsrc,
                          const float* __restrict__ as_,
                          const float* __restrict__ ad_,
                          float* __restrict__ alpha,
                          float* __restrict__ inv_) {
    int d = (blockIdx.x * blockDim.x + threadIdx.x) >> 5;
    int lane = threadIdx.x & 31;
    if (d >= NN) return;
    int s0 = rowptr[d], s1 = rowptr[d + 1];
    float4 ad4 = *(const float4*)&ad_[d * 4];

    float4 mx = make_float4(-3e38f, -3e38f, -3e38f, -3e38f);
    for (int p = s0 + lane; p < s1; p += 32) {
        int src = csrsrc[p];
        float4 g = *(const float4*)&as_[src * 4];
        float4 e;
        e.x = leaky(g.x + ad4.x);
        e.y = leaky(g.y + ad4.y);
        e.z = leaky(g.z + ad4.z);
        e.w = leaky(g.w + ad4.w);
        *(float4*)&alpha[(size_t)p * 4] = e;
        mx.x = fmaxf(mx.x, e.x); mx.y = fmaxf(mx.y, e.y);
        mx.z = fmaxf(mx.z, e.z); mx.w = fmaxf(mx.w, e.w);
    }
    #pragma unroll
    for (int o = 16; o > 0; o >>= 1) {
        mx.x = fmaxf(mx.x, __shfl_xor_sync(0xffffffffu, mx.x, o));
        mx.y = fmaxf(mx.y, __shfl_xor_sync(0xffffffffu, mx.y, o));
        mx.z = fmaxf(mx.z, __shfl_xor_sync(0xffffffffu, mx.z, o));
        mx.w = fmaxf(mx.w, __shfl_xor_sync(0xffffffffu, mx.w, o));
    }

    float4 sum = make_float4(0.f, 0.f, 0.f, 0.f);
    for (int p = s0 + lane; p < s1; p += 32) {
        float4 e = *(const float4*)&alpha[(size_t)p * 4];
        float4 ex;
        ex.x = expf(e.x - mx.x); ex.y = expf(e.y - mx.y);
        ex.z = expf(e.z - mx.z); ex.w = expf(e.w - mx.w);
        *(float4*)&alpha[(size_t)p * 4] = ex;
        sum.x += ex.x; sum.y += ex.y; sum.z += ex.z; sum.w += ex.w;
    }
    #pragma unroll
    for (int o = 16; o > 0; o >>= 1) {
        sum.x += __shfl_xor_sync(0xffffffffu, sum.x, o);
        sum.y += __shfl_xor_sync(0xffffffffu, sum.y, o);
        sum.z += __shfl_xor_sync(0xffffffffu, sum.z, o);
        sum.w += __shfl_xor_sync(0xffffffffu, sum.w, o);
    }
    if (lane == 0) {
        float4 inv;
        inv.x = 1.f / sum.x; inv.y = 1.f / sum.y;
        inv.z = 1.f / sum.z; inv.w = 1.f / sum.w;
        *(float4*)&inv_[d * 4] = inv;
    }
}

__global__ __launch_bounds__(256)
void edge_softmax1_kernel(const int* __restrict__ rowptr,
                          const int* __restrict__ csrsrc,
                          const float* __restrict__ as_,
                          const float* __restrict__ ad_,
                          float* __restrict__ alpha,
                          float* __restrict__ inv_) {
    int d = (blockIdx.x * blockDim.x + threadIdx.x) >> 5;
    int lane = threadIdx.x & 31;
    if (d >= NN) return;
    int s0 = rowptr[d], s1 = rowptr[d + 1];
    float adv = ad_[d];

    float mx = -3e38f;
    for (int p = s0 + lane; p < s1; p += 32) {
        float e = leaky(as_[csrsrc[p]] + adv);
        alpha[p] = e;
        mx = fmaxf(mx, e);
    }
    #pragma unroll
    for (int o = 16; o > 0; o >>= 1)
        mx = fmaxf(mx, __shfl_xor_sync(0xffffffffu, mx, o));

    float sum = 0.f;
    for (int p = s0 + lane; p < s1; p += 32) {
        float ex = expf(alpha[p] - mx);
        alpha[p] = ex;
        sum += ex;
    }
    #pragma unroll
    for (int o = 16; o > 0; o >>= 1)
        sum += __shfl_xor_sync(0xffffffffu, sum, o);
    if (lane == 0) inv_[d] = 1.f / sum;
}

// ---- aggregation: out = relu(inv * sum ex*h16 + b); 4-edge unroll ---------
template <bool F16OUT>
__global__ __launch_bounds__(256)
void aggregate_kernel(const __half* __restrict__ h,
                      const float* __restrict__ alpha,
                      const float* __restrict__ inv_,
                      const int* __restrict__ rowptr,
                      const int* __restrict__ csrsrc,
                      const float* __restrict__ bias,
                      float* __restrict__ out32,
                      __half* __restrict__ out16,
                      int H, int HC, int logC) {
    int d = blockIdx.x * blockDim.y + threadIdx.y;
    if (d >= NN) return;
    int f = threadIdx.x * 4;
    int head = f >> logC;

    float acc0 = 0.f, acc1 = 0.f, acc2 = 0.f, acc3 = 0.f;
    int s0 = rowptr[d], s1 = rowptr[d + 1];
    int p = s0;
    for (; p + 3 < s1; p += 4) {
        int sA = csrsrc[p],     sB = csrsrc[p + 1];
        int sC = csrsrc[p + 2], sD = csrsrc[p + 3];
        float aA = alpha[(size_t)p * H + head];
        float aB = alpha[(size_t)(p + 1) * H + head];
        float aC = alpha[(size_t)(p + 2) * H + head];
        float aD = alpha[(size_t)(p + 3) * H + head];
        uint2 rA = *(const uint2*)&h[(size_t)sA * HC + f];
        uint2 rB = *(const uint2*)&h[(size_t)sB * HC + f];
        uint2 rC = *(const uint2*)&h[(size_t)sC * HC + f];
        uint2 rD = *(const uint2*)&h[(size_t)sD * HC + f];
        float2 vA0 = __half22float2(*(__half2*)&rA.x);
        float2 vA1 = __half22float2(*(__half2*)&rA.y);
        float2 vB0 = __half22float2(*(__half2*)&rB.x);
        float2 vB1 = __half22float2(*(__half2*)&rB.y);
        float2 vC0 = __half22float2(*(__half2*)&rC.x);
        float2 vC1 = __half22float2(*(__half2*)&rC.y);
        float2 vD0 = __half22float2(*(__half2*)&rD.x);
        float2 vD1 = __half22float2(*(__half2*)&rD.y);
        acc0 = fmaf(vA0.x, aA, fmaf(vB0.x, aB, fmaf(vC0.x, aC, fmaf(vD0.x, aD, acc0))));
        acc1 = fmaf(vA0.y, aA, fmaf(vB0.y, aB, fmaf(vC0.y, aC, fmaf(vD0.y, aD, acc1))));
        acc2 = fmaf(vA1.x, aA, fmaf(vB1.x, aB, fmaf(vC1.x, aC, fmaf(vD1.x, aD, acc2))));
        acc3 = fmaf(vA1.y, aA, fmaf(vB1.y, aB, fmaf(vC1.y, aC, fmaf(vD1.y, aD, acc3))));
    }
    for (; p < s1; p++) {
        int src = csrsrc[p];
        float a = alpha[(size_t)p * H + head];
        uint2 raw = *(const uint2*)&h[(size_t)src * HC + f];
        float2 v0 = __half22float2(*(__half2*)&raw.x);
        float2 v1 = __half22float2(*(__half2*)&raw.y);
        acc0 = fmaf(v0.x, a, acc0);
        acc1 = fmaf(v0.y, a, acc1);
        acc2 = fmaf(v1.x, a, acc2);
        acc3 = fmaf(v1.y, a, acc3);
    }

    float inv = inv_[d * H + head];
    float4 b = *(const float4*)&bias[f];
    float o0 = fmaxf(fmaf(acc0, inv, b.x), 0.f);
    float o1 = fmaxf(fmaf(acc1, inv, b.y), 0.f);
    float o2 = fmaxf(fmaf(acc2, inv, b.z), 0.f);
    float o3 = fmaxf(fmaf(acc3, inv, b.w), 0.f);
    if (F16OUT) {
        uint2 packed;
        *(__half2*)&packed.x = __floats2half2_rn(o0, o1);
        *(__half2*)&packed.y = __floats2half2_rn(o2, o3);
        *(uint2*)&out16[(size_t)d * HC + f] = packed;
    } else {
        float4 o = make_float4(o0, o1, o2, o3);
        *(float4*)&out32[(size_t)d * HC + f] = o;
    }
}

// ---------------------------------------------------------------------------
// host side
// ---------------------------------------------------------------------------
static inline void run_gemm(const __half* A, const __half* Bt, __half* C,
                            const float* a_s, const float* a_d,
                            float* out_s, float* out_d,
                            int N, int K, int H, int logC) {
    dim3 grid((N + TBN - 1) / TBN, NPAD / TBM);
    h16gemm_kernel<<<grid, 256, GEMM_SMEM>>>(A, Bt, C, a_s, a_d, out_s, out_d,
                                             N, K, H, logC);
}

static inline void run_aggregate(const __half* h, const float* alpha,
                                 const float* inv_,
                                 const int* rowptr, const int* csrsrc,
                                 const float* bias, float* out32,
                                 __half* out16, int H, int HC, int logC) {
    int tx = HC / 4;
    int ty = 256 / tx;
    dim3 block(tx, ty);
    dim3 grid((NN + ty - 1) / ty);
    if (out16)
        aggregate_kernel<true><<<grid, block>>>(h, alpha, inv_, rowptr, csrsrc,
                                                bias, nullptr, out16, H, HC, logC);
    else
        aggregate_kernel<false><<<grid, block>>>(h, alpha, inv_, rowptr, csrsrc,
                                                 bias, out32, nullptr, H, HC, logC);
}

extern "C" void kernel_launch(void* const* d_in, const int* in_sizes, int n_in,
                              void* d_out, int out_size) {
    const float* x   = (const float*)d_in[0];
    const void*  ei  = d_in[1];
    const float* W1  = (const float*)d_in[2];
    const float* a1s = (const float*)d_in[3];
    const float* a1d = (const float*)d_in[4];
    const float* b1  = (const float*)d_in[5];
    const float* W2  = (const float*)d_in[6];
    const float* a2s = (const float*)d_in[7];
    const float* a2d = (const float*)d_in[8];
    const float* b2  = (const float*)d_in[9];
    const float* W3  = (const float*)d_in[10];
    const float* a3s = (const float*)d_in[11];
    const float* a3d = (const float*)d_in[12];
    const float* b3  = (const float*)d_in[13];
    const float* W4  = (const float*)d_in[14];
    const float* a4s = (const float*)d_in[15];
    const float* a4d = (const float*)d_in[16];
    const float* b4  = (const float*)d_in[17];
    float* out = (float*)d_out;

    static bool attr_set = false;
    if (!attr_set) {
        cudaFuncSetAttribute(h16gemm_kernel,
                             cudaFuncAttributeMaxDynamicSharedMemorySize,
                             GEMM_SMEM);
        attr_set = true;
    }

    float *asb, *adb, *invb, *alpha;
    __half *hA, *hB, *wt;
    int *deg, *rowptr, *cursor, *csrsrc, *is64;
    cudaGetSymbolAddress((void**)&hA, g_hA);
    cudaGetSymbolAddress((void**)&hB, g_hB);
    cudaGetSymbolAddress((void**)&wt, g_wt);
    cudaGetSymbolAddress((void**)&asb, g_as);
    cudaGetSymbolAddress((void**)&adb, g_ad);
    cudaGetSymbolAddress((void**)&invb, g_inv);
    cudaGetSymbolAddress((void**)&alpha, g_alpha);
    cudaGetSymbolAddress((void**)&deg, g_deg);
    cudaGetSymbolAddress((void**)&rowptr, g_rowptr);
    cudaGetSymbolAddress((void**)&cursor, g_cursor);
    cudaGetSymbolAddress((void**)&csrsrc, g_csrsrc);
    cudaGetSymbolAddress((void**)&is64, g_is64);

    __half* wt1 = wt;                     // [512][256]
    __half* wt2 = wt + 131072;            // [512][512]
    __half* wt3 = wt + 131072 + 262144;   // [256][512]
    __half* wt4 = wt + 131072 + 262144 + 131072;  // [64][256]

    // ---- prep: CSR + dtype conversions ----
    cudaMemsetAsync(deg, 0, NN * sizeof(int));
    detect64_kernel<<<1, 32>>>((const int*)ei, is64);
    count_deg_kernel<<<(E_TOT + 255) / 256, 256>>>(ei, is64, deg);
    scan_kernel<<<1, 1024>>>(deg, rowptr, NN);
    cudaMemcpyAsync(cursor, rowptr, NN * sizeof(int), cudaMemcpyDeviceToDevice);
    fill_csr_kernel<<<(E_TOT + 255) / 256, 256>>>(ei, is64, cursor, csrsrc);

    f2h_kernel<<<(NN * 256 / 4 + 255) / 256, 256>>>(x, hA, NN * 256);
    {
        WtJob j1{W1, wt1, 256, 512};
        WtJob j2{W2, wt2, 512, 512};
        WtJob j3{W3, wt3, 512, 256};
        WtJob j4{W4, wt4, 256, 64};
        transpose_all_kernel<<<dim3(16, 16, 4), dim3(32, 8)>>>(j1, j2, j3, j4);
    }

    auto nblocks_warps = [](int warps) { return (warps + 7) / 8; };

    // ---- layer 1: 256 -> 4x128 ----
    run_gemm(hA, wt1, hB, a1s, a1d, asb, adb, 512, 256, 4, 7);
    edge_softmax4_kernel<<<nblocks_warps(NN), 256>>>(rowptr, csrsrc, asb, adb, alpha, invb);
    run_aggregate(hB, alpha, invb, rowptr, csrsrc, b1, nullptr, hA, 4, 512, 7);

    // ---- layer 2: 512 -> 4x128 ----
    run_gemm(hA, wt2, hB, a2s, a2d, asb, adb, 512, 512, 4, 7);
    edge_softmax4_kernel<<<nblocks_warps(NN), 256>>>(rowptr, csrsrc, asb, adb, alpha, invb);
    run_aggregate(hB, alpha, invb, rowptr, csrsrc, b2, nullptr, hA, 4, 512, 7);

    // ---- layer 3: 512 -> 4x64 ----
    run_gemm(hA, wt3, hB, a3s, a3d, asb, adb, 256, 512, 4, 6);
    edge_softmax4_kernel<<<nblocks_warps(NN), 256>>>(rowptr, csrsrc, asb, adb, alpha, invb);
    run_aggregate(hB, alpha, invb, rowptr, csrsrc, b3, nullptr, hA, 4, 256, 6);

    // ---- layer 4: 256 -> 1x64, concat=False ----
    run_gemm(hA, wt4, hB, a4s, a4d, asb, adb, 64, 256, 1, 6);
    edge_softmax1_kernel<<<nblocks_warps(NN), 256>>>(rowptr, csrsrc, asb, adb, alpha, invb);
    run_aggregate(hB, alpha, invb, rowptr, csrsrc, b4, out, nullptr, 1, 64, 6);

    (void)in_sizes; (void)n_in; (void)out_size;
}

// round 11
// speedup vs baseline: 1.4312x; 1.0428x over previous
#include <cuda_runtime.h>
#include <cuda_fp16.h>
#include <cstdint>
#include <math.h>

// ---------------------------------------------------------------------------
// GAT 4-layer stack on GB300, round 11 (round-10 + overlap):
//  - CSR build chain forked onto a side stream, overlapped with
//    f2h/transpose/GEMM1 (event fork/join, capture-legal)
//  - cursor init folded into scan kernel (memcpy node deleted)
// ---------------------------------------------------------------------------

#define NN      30000
#define NPAD    30080
#define E_RAW   480000
#define E_TOT   (E_RAW + NN)
#define MAXF    512
#define NEG_SLOPE 0.2f

// ---- scratch (device globals; zero-initialized at load) -------------------
__device__ __half g_hA[NPAD * MAXF];            // fp16 activations ping
__device__ __half g_hB[NPAD * MAXF];            // fp16 activations pong
__device__ __half g_wt[540672];                 // transposed fp16 weights
__device__ float  g_as[NN * 4];
__device__ float  g_ad[NN * 4];
__device__ float  g_inv[NN * 4];                // 1/den per (dst,head)
__device__ float  g_alpha[(size_t)E_TOT * 4];   // unnormalized exp weights
__device__ int    g_deg[NN];
__device__ int    g_rowptr[NN + 1];
__device__ int    g_cursor[NN];
__device__ int    g_csrsrc[E_TOT];
__device__ int    g_is64;

// ---------------------------------------------------------------------------
// edge_index dtype detection (int32 vs int64)
// ---------------------------------------------------------------------------
__global__ void detect64_kernel(const int* __restrict__ words, int* flag) {
    if (threadIdx.x == 0 && blockIdx.x == 0) {
        int any = 0;
        #pragma unroll 4
        for (int i = 0; i < 256; i++) any |= words[2 * i + 1];
        *flag = (any == 0) ? 1 : 0;
    }
}

__device__ __forceinline__ void get_edge(const void* ei, int e, int is64,
                                         int& src, int& dst) {
    if (e >= E_RAW) { src = dst = e - E_RAW; return; }
    if (is64) {
        const long long* p = (const long long*)ei;
        src = (int)p[e];
        dst = (int)p[E_RAW + e];
    } else {
        const int* p = (const int*)ei;
        src = p[e];
        dst = p[E_RAW + e];
    }
}

// ---- CSR build ------------------------------------------------------------
__global__ void count_deg_kernel(const void* __restrict__ ei,
                                 const int* __restrict__ flag,
                                 int* __restrict__ deg) {
    int e = blockIdx.x * blockDim.x + threadIdx.x;
    if (e >= E_TOT) return;
    int src, dst;
    get_edge(ei, e, *flag, src, dst);
    atomicAdd(&deg[dst], 1);
}

// shuffle-based block scan; writes rowptr AND cursor (exclusive prefix)
__global__ void scan_kernel(const int* __restrict__ deg,
                            int* __restrict__ rowptr,
                            int* __restrict__ cursor, int n) {
    __shared__ int warpsums[32];
    __shared__ int carry_s;
    int t = threadIdx.x;
    int lane = t & 31;
    int w = t >> 5;
    if (t == 0) carry_s = 0;
    __syncthreads();
    for (int base = 0; base < n; base += 1024) {
        int i = base + t;
        int v = (i < n) ? deg[i] : 0;
        int x = v;
        #pragma unroll
        for (int o = 1; o < 32; o <<= 1) {
            int u = __shfl_up_sync(0xffffffffu, x, o);
            if (lane >= o) x += u;
        }
        if (lane == 31) warpsums[w] = x;
        __syncthreads();
        if (w == 0) {
            int s = warpsums[lane];
            #pragma unroll
            for (int o = 1; o < 32; o <<= 1) {
                int u = __shfl_up_sync(0xffffffffu, s, o);
                if (lane >= o) s += u;
            }
            warpsums[lane] = s;
        }
        __syncthreads();
        int woff = (w > 0) ? warpsums[w - 1] : 0;
        int incl = x + woff + carry_s;
        if (i < n) {
            int ex = incl - v;
            rowptr[i] = ex;
            cursor[i] = ex;
        }
        __syncthreads();
        if (t == 1023) carry_s = incl;
        __syncthreads();
    }
    if (t == 0) rowptr[n] = carry_s;
}

__global__ void fill_csr_kernel(const void* __restrict__ ei,
                                const int* __restrict__ flag,
                                int* __restrict__ cursor,
                                int* __restrict__ csrsrc) {
    int e = blockIdx.x * blockDim.x + threadIdx.x;
    if (e >= E_TOT) return;
    int src, dst;
    get_edge(ei, e, *flag, src, dst);
    int pos = atomicAdd(&cursor[dst], 1);
    csrsrc[pos] = src;
}

// ---- prep: fp32 -> fp16 convert, fused weight transposes ------------------
__global__ void f2h_kernel(const float* __restrict__ in,
                           __half* __restrict__ out, int n) {
    int i = blockIdx.x * blockDim.x + threadIdx.x;
    int i4 = i * 4;
    if (i4 + 3 < n) {
        float4 v = *(const float4*)&in[i4];
        __half2 lo = __floats2half2_rn(v.x, v.y);
        __half2 hi = __floats2half2_rn(v.z, v.w);
        *(__half2*)&out[i4] = lo;
        *(__half2*)&out[i4 + 2] = hi;
    } else {
        for (int j = i4; j < n; j++) out[j] = __float2half_rn(in[j]);
    }
}

struct WtJob { const float* W; __half* Wt; int K, N; };

__global__ void transpose_all_kernel(WtJob j0, WtJob j1, WtJob j2, WtJob j3) {
    WtJob j = (blockIdx.z == 0) ? j0 : (blockIdx.z == 1) ? j1
            : (blockIdx.z == 2) ? j2 : j3;
    int k0 = blockIdx.y * 32, n0 = blockIdx.x * 32;
    if (k0 >= j.K || n0 >= j.N) return;
    __shared__ float tile[32][33];
    int tx = threadIdx.x, ty = threadIdx.y;
    for (int i = ty; i < 32; i += 8) {
        int k = k0 + i, n = n0 + tx;
        tile[i][tx] = (k < j.K && n < j.N) ? j.W[(size_t)k * j.N + n] : 0.f;
    }
    __syncthreads();
    for (int i = ty; i < 32; i += 8) {
        int n = n0 + i, k = k0 + tx;
        if (n < j.N && k < j.K)
            j.Wt[(size_t)n * j.K + k] = __float2half_rn(tile[tx][i]);
    }
}

// ---------------------------------------------------------------------------
// fp16 tensor-core GEMM + fused attention-logit epilogue.
// 3-stage cp.async pipeline, dynamic smem.
// ---------------------------------------------------------------------------
#define TBM 128
#define TBN 128
#define TBK 32
#define SAH 40
#define GEMM_SMEM (3 * (TBM + TBN) * SAH * 2)   // 61440 bytes

__device__ __forceinline__ void cp16(unsigned int smem, const void* gptr, int sz) {
    asm volatile("cp.async.cg.shared.global [%0], [%1], 16, %2;\n"
                 :: "r"(smem), "l"(gptr), "r"(sz));
}

__device__ __forceinline__ unsigned int smem_u32(const void* p) {
    return (unsigned int)__cvta_generic_to_shared(p);
}

__device__ __forceinline__ void mma_f16(float* d, const unsigned* a,
                                        const unsigned* b) {
    asm volatile(
        "mma.sync.aligned.m16n8k16.row.col.f32.f16.f16.f32 "
        "{%0,%1,%2,%3}, {%4,%5,%6,%7}, {%8,%9}, {%0,%1,%2,%3};\n"
        : "+f"(d[0]), "+f"(d[1]), "+f"(d[2]), "+f"(d[3])
        : "r"(a[0]), "r"(a[1]), "r"(a[2]), "r"(a[3]),
          "r"(b[0]), "r"(b[1]));
}

__global__ __launch_bounds__(256, 2)
void h16gemm_kernel(const __half* __restrict__ A, const __half* __restrict__ Bt,
                    __half* __restrict__ C,
                    const float* __restrict__ a_s, const float* __restrict__ a_d,
                    float* __restrict__ out_s, float* __restrict__ out_d,
                    int N, int K, int H, int logC) {
    extern __shared__ __align__(16) char dsm[];
    __half* As = (__half*)dsm;                  // [3][TBM*SAH]
    __half* Bs = As + 3 * TBM * SAH;            // [3][TBN*SAH]
    float* s_av  = (float*)dsm;                 // [2][TBN]  (epilogue alias)
    float* tmp_s = s_av + 2 * TBN;              // [4][128]
    float* tmp_d = tmp_s + 4 * 128;             // [4][128]

    int tid  = threadIdx.x;
    int bm   = blockIdx.y * TBM;
    int bn   = blockIdx.x * TBN;
    int warp = tid >> 5;
    int lane = tid & 31;
    int wm   = (warp & 1) * 64;
    int wn   = (warp >> 1) * 32;
    int wnq  = warp >> 1;
    int r    = lane >> 2;
    int c    = lane & 3;

    float acc[4][4][4];
    #pragma unroll
    for (int mi = 0; mi < 4; mi++)
        #pragma unroll
        for (int ni = 0; ni < 4; ni++)
            #pragma unroll
            for (int q = 0; q < 4; q++) acc[mi][ni][q] = 0.f;

    int row0 = tid >> 1;
    int kc0  = (tid & 1) * 2;
    int niter = K / TBK;

    auto stage = [&](int buf, int k0) {
        #pragma unroll
        for (int j = 0; j < 2; j++) {
            int kc = kc0 + j;
            int smoff = (row0 * SAH + kc * 8) * 2;
            const __half* ga = A + (size_t)(bm + row0) * K + k0 + kc * 8;
            cp16(smem_u32(&As[buf * TBM * SAH]) + smoff, ga, 16);
            int rb = bn + row0;
            const __half* gb = Bt + (size_t)(rb < N ? rb : 0) * K + k0 + kc * 8;
            cp16(smem_u32(&Bs[buf * TBN * SAH]) + smoff, gb, rb < N ? 16 : 0);
        }
        asm volatile("cp.async.commit_group;\n");
    };

    stage(0, 0);
    stage(1, TBK);

    for (int it = 0; it < niter; it++) {
        if (it < niter - 1) {
            asm volatile("cp.async.wait_group 1;\n");
        } else {
            asm volatile("cp.async.wait_group 0;\n");
        }
        __syncthreads();
        if (it + 2 < niter) stage((it + 2) % 3, (it + 2) * TBK);

        int buf = it % 3;
        const __half* Ab = &As[buf * TBM * SAH];
        const __half* Bb = &Bs[buf * TBN * SAH];
        #pragma unroll
        for (int kk = 0; kk < 2; kk++) {
            int kb = kk * 16;
            unsigned af[4][4];
            #pragma unroll
            for (int mi = 0; mi < 4; mi++) {
                const __half* ap = &Ab[(wm + mi * 16 + r) * SAH + kb + 2 * c];
                af[mi][0] = *(const unsigned*)(ap);
                af[mi][1] = *(const unsigned*)(ap + 8 * SAH);
                af[mi][2] = *(const unsigned*)(ap + 8);
                af[mi][3] = *(const unsigned*)(ap + 8 * SAH + 8);
            }
            unsigned bf[4][2];
            #pragma unroll
            for (int ni = 0; ni < 4; ni++) {
                const __half* bp = &Bb[(wn + ni * 8 + r) * SAH + kb + 2 * c];
                bf[ni][0] = *(const unsigned*)(bp);
                bf[ni][1] = *(const unsigned*)(bp + 8);
            }
            #pragma unroll
            for (int mi = 0; mi < 4; mi++)
                #pragma unroll
                for (int ni = 0; ni < 4; ni++)
                    mma_f16(acc[mi][ni], af[mi], bf[ni]);
        }
    }
    __syncthreads();   // all compute done before epilogue aliases smem

    // ---- store h (fp16) ----
    #pragma unroll
    for (int mi = 0; mi < 4; mi++) {
        int m0 = bm + wm + mi * 16 + r;
        #pragma unroll
        for (int ni = 0; ni < 4; ni++) {
            int n0 = bn + wn + ni * 8 + 2 * c;
            if (n0 < N) {
                __half2 v0 = __floats2half2_rn(acc[mi][ni][0], acc[mi][ni][1]);
                *(__half2*)&C[(size_t)m0 * N + n0] = v0;
                __half2 v1 = __floats2half2_rn(acc[mi][ni][2], acc[mi][ni][3]);
                *(__half2*)&C[(size_t)(m0 + 8) * N + n0] = v1;
            }
        }
    }

    // ---- fused logits ----
    if (tid < TBN) {
        int gcol = bn + tid;
        s_av[tid] = (gcol < N) ? a_s[gcol] : 0.f;
    } else {
        int gcol = bn + tid - TBN;
        s_av[TBN + tid - TBN] = (gcol < N) ? a_d[gcol] : 0.f;
    }
    __syncthreads();

    float ps[4][2], pd[4][2];
    #pragma unroll
    for (int mi = 0; mi < 4; mi++) {
        ps[mi][0] = ps[mi][1] = 0.f;
        pd[mi][0] = pd[mi][1] = 0.f;
    }
    #pragma unroll
    for (int mi = 0; mi < 4; mi++)
        #pragma unroll
        for (int ni = 0; ni < 4; ni++)
            #pragma unroll
            for (int q = 0; q < 4; q++) {
                int col = wn + ni * 8 + 2 * c + (q & 1);
                int hf = q >> 1;
                ps[mi][hf] = fmaf(acc[mi][ni][q], s_av[col], ps[mi][hf]);
                pd[mi][hf] = fmaf(acc[mi][ni][q], s_av[TBN + col], pd[mi][hf]);
            }
    #pragma unroll
    for (int mi = 0; mi < 4; mi++)
        #pragma unroll
        for (int hf = 0; hf < 2; hf++) {
            float vs = ps[mi][hf], vd = pd[mi][hf];
            vs += __shfl_xor_sync(0xffffffffu, vs, 1);
            vs += __shfl_xor_sync(0xffffffffu, vs, 2);
            vd += __shfl_xor_sync(0xffffffffu, vd, 1);
            vd += __shfl_xor_sync(0xffffffffu, vd, 2);
            if (c == 0) {
                int row = wm + mi * 16 + r + hf * 8;
                tmp_s[wnq * 128 + row] = vs;
                tmp_d[wnq * 128 + row] = vd;
            }
        }
    __syncthreads();

    int hpb = TBN >> logC;
    int gph = 4 / hpb;
    if (tid < 128) {
        int row = tid, n = bm + row;
        if (n < NN) {
            for (int hl = 0; hl < hpb; hl++) {
                int colbase = hl << logC;
                if (bn + colbase < N) {
                    float sum = 0.f;
                    for (int g = 0; g < gph; g++)
                        sum += tmp_s[(hl * gph + g) * 128 + row];
                    int head = (bn + colbase) >> logC;
                    out_s[n * H + head] = sum;
                }
            }
        }
    } else {
        int row = tid - 128, n = bm + row;
        if (n < NN) {
            for (int hl = 0; hl < hpb; hl++) {
                int colbase = hl << logC;
                if (bn + colbase < N) {
                    float sum = 0.f;
                    for (int g = 0; g < gph; g++)
                        sum += tmp_d[(hl * gph + g) * 128 + row];
                    int head = (bn + colbase) >> logC;
                    out_d[n * H + head] = sum;
                }
            }
        }
    }
}

// ---- head-combined edge softmax (2 passes; inv stored) --------------------
__device__ __forceinline__ float leaky(float x) {
    return x > 0.f ? x : NEG_SLOPE * x;
}

__global__ __launch_bounds__(256)
void edge_softmax4_kernel(const int* __restrict__ rowptr,
                          const int* __restrict__ csrsrc,
                          const float* __restrict__ as_,
                          const float* __restrict__ ad_,
                          float* __restrict__ alpha,
                          float* __restrict__ inv_) {
    int d = (blockIdx.x * blockDim.x + threadIdx.x) >> 5;
    int lane = threadIdx.x & 31;
    if (d >= NN) return;
    int s0 = rowptr[d], s1 = rowptr[d + 1];
    float4 ad4 = *(const float4*)&ad_[d * 4];

    float4 mx = make_float4(-3e38f, -3e38f, -3e38f, -3e38f);
    for (int p = s0 + lane; p < s1; p += 32) {
        int src = csrsrc[p];
        float4 g = *(const float4*)&as_[src * 4];
        float4 e;
        e.x = leaky(g.x + ad4.x);
        e.y = leaky(g.y + ad4.y);
        e.z = leaky(g.z + ad4.z);
        e.w = leaky(g.w + ad4.w);
        *(float4*)&alpha[(size_t)p * 4] = e;
        mx.x = fmaxf(mx.x, e.x); mx.y = fmaxf(mx.y, e.y);
        mx.z = fmaxf(mx.z, e.z); mx.w = fmaxf(mx.w, e.w);
    }
    #pragma unroll
    for (int o = 16; o > 0; o >>= 1) {
        mx.x = fmaxf(mx.x, __shfl_xor_sync(0xffffffffu, mx.x, o));
        mx.y = fmaxf(mx.y, __shfl_xor_sync(0xffffffffu, mx.y, o));
        mx.z = fmaxf(mx.z, __shfl_xor_sync(0xffffffffu, mx.z, o));
        mx.w = fmaxf(mx.w, __shfl_xor_sync(0xffffffffu, mx.w, o));
    }

    float4 sum = make_float4(0.f, 0.f, 0.f, 0.f);
    for (int p = s0 + lane; p < s1; p += 32) {
        float4 e = *(const float4*)&alpha[(size_t)p * 4];
        float4 ex;
        ex.x = expf(e.x - mx.x); ex.y = expf(e.y - mx.y);
        ex.z = expf(e.z - mx.z); ex.w = expf(e.w - mx.w);
        *(float4*)&alpha[(size_t)p * 4] = ex;
        sum.x += ex.x; sum.y += ex.y; sum.z += ex.z; sum.w += ex.w;
    }
    #pragma unroll
    for (int o = 16; o > 0; o >>= 1) {
        sum.x += __shfl_xor_sync(0xffffffffu, sum.x, o);
        sum.y += __shfl_xor_sync(0xffffffffu, sum.y, o);
        sum.z += __shfl_xor_sync(0xffffffffu, sum.z, o);
        sum.w += __shfl_xor_sync(0xffffffffu, sum.w, o);
    }
    if (lane == 0) {
        float4 inv;
        inv.x = 1.f / sum.x; inv.y = 1.f / sum.y;
        inv.z = 1.f / sum.z; inv.w = 1.f / sum.w;
        *(float4*)&inv_[d * 4] = inv;
    }
}

__global__ __launch_bounds__(256)
void edge_softmax1_kernel(const int* __restrict__ rowptr,
                          const int* __restrict__ csrsrc,
                          const float* __restrict__ as_,
                          const float* __restrict__ ad_,
                          float* __restrict__ alpha,
                          float* __restrict__ inv_) {
    int d = (blockIdx.x * blockDim.x + threadIdx.x) >> 5;
    int lane = threadIdx.x & 31;
    if (d >= NN) return;
    int s0 = rowptr[d], s1 = rowptr[d + 1];
    float adv = ad_[d];

    float mx = -3e38f;
    for (int p = s0 + lane; p < s1; p += 32) {
        float e = leaky(as_[csrsrc[p]] + adv);
        alpha[p] = e;
        mx = fmaxf(mx, e);
    }
    #pragma unroll
    for (int o = 16; o > 0; o >>= 1)
        mx = fmaxf(mx, __shfl_xor_sync(0xffffffffu, mx, o));

    float sum = 0.f;
    for (int p = s0 + lane; p < s1; p += 32) {
        float ex = expf(alpha[p] - mx);
        alpha[p] = ex;
        sum += ex;
    }
    #pragma unroll
    for (int o = 16; o > 0; o >>= 1)
        sum += __shfl_xor_sync(0xffffffffu, sum, o);
    if (lane == 0) inv_[d] = 1.f / sum;
}

// ---- aggregation: out = relu(inv * sum ex*h16 + b); 4-edge unroll ---------
template <bool F16OUT>
__global__ __launch_bounds__(256)
void aggregate_kernel(const __half* __restrict__ h,
                      const float* __restrict__ alpha,
                      const float* __restrict__ inv_,
                      const int* __restrict__ rowptr,
                      const int* __restrict__ csrsrc,
                      const float* __restrict__ bias,
                      float* __restrict__ out32,
                      __half* __restrict__ out16,
                      int H, int HC, int logC) {
    int d = blockIdx.x * blockDim.y + threadIdx.y;
    if (d >= NN) return;
    int f = threadIdx.x * 4;
    int head = f >> logC;

    float acc0 = 0.f, acc1 = 0.f, acc2 = 0.f, acc3 = 0.f;
    int s0 = rowptr[d], s1 = rowptr[d + 1];
    int p = s0;
    for (; p + 3 < s1; p += 4) {
        int sA = csrsrc[p],     sB = csrsrc[p + 1];
        int sC = csrsrc[p + 2], sD = csrsrc[p + 3];
        float aA = alpha[(size_t)p * H + head];
        float aB = alpha[(size_t)(p + 1) * H + head];
        float aC = alpha[(size_t)(p + 2) * H + head];
        float aD = alpha[(size_t)(p + 3) * H + head];
        uint2 rA = *(const uint2*)&h[(size_t)sA * HC + f];
        uint2 rB = *(const uint2*)&h[(size_t)sB * HC + f];
        uint2 rC = *(const uint2*)&h[(size_t)sC * HC + f];
        uint2 rD = *(const uint2*)&h[(size_t)sD * HC + f];
        float2 vA0 = __half22float2(*(__half2*)&rA.x);
        float2 vA1 = __half22float2(*(__half2*)&rA.y);
        float2 vB0 = __half22float2(*(__half2*)&rB.x);
        float2 vB1 = __half22float2(*(__half2*)&rB.y);
        float2 vC0 = __half22float2(*(__half2*)&rC.x);
        float2 vC1 = __half22float2(*(__half2*)&rC.y);
        float2 vD0 = __half22float2(*(__half2*)&rD.x);
        float2 vD1 = __half22float2(*(__half2*)&rD.y);
        acc0 = fmaf(vA0.x, aA, fmaf(vB0.x, aB, fmaf(vC0.x, aC, fmaf(vD0.x, aD, acc0))));
        acc1 = fmaf(vA0.y, aA, fmaf(vB0.y, aB, fmaf(vC0.y, aC, fmaf(vD0.y, aD, acc1))));
        acc2 = fmaf(vA1.x, aA, fmaf(vB1.x, aB, fmaf(vC1.x, aC, fmaf(vD1.x, aD, acc2))));
        acc3 = fmaf(vA1.y, aA, fmaf(vB1.y, aB, fmaf(vC1.y, aC, fmaf(vD1.y, aD, acc3))));
    }
    for (; p < s1; p++) {
        int src = csrsrc[p];
        float a = alpha[(size_t)p * H + head];
        uint2 raw = *(const uint2*)&h[(size_t)src * HC + f];
        float2 v0 = __half22float2(*(__half2*)&raw.x);
        float2 v1 = __half22float2(*(__half2*)&raw.y);
        acc0 = fmaf(v0.x, a, acc0);
        acc1 = fmaf(v0.y, a, acc1);
        acc2 = fmaf(v1.x, a, acc2);
        acc3 = fmaf(v1.y, a, acc3);
    }

    float inv = inv_[d * H + head];
    float4 b = *(const float4*)&bias[f];
    float o0 = fmaxf(fmaf(acc0, inv, b.x), 0.f);
    float o1 = fmaxf(fmaf(acc1, inv, b.y), 0.f);
    float o2 = fmaxf(fmaf(acc2, inv, b.z), 0.f);
    float o3 = fmaxf(fmaf(acc3, inv, b.w), 0.f);
    if (F16OUT) {
        uint2 packed;
        *(__half2*)&packed.x = __floats2half2_rn(o0, o1);
        *(__half2*)&packed.y = __floats2half2_rn(o2, o3);
        *(uint2*)&out16[(size_t)d * HC + f] = packed;
    } else {
        float4 o = make_float4(o0, o1, o2, o3);
        *(float4*)&out32[(size_t)d * HC + f] = o;
    }
}

// ---------------------------------------------------------------------------
// host side
// ---------------------------------------------------------------------------
static inline void run_gemm(const __half* A, const __half* Bt, __half* C,
                            const float* a_s, const float* a_d,
                            float* out_s, float* out_d,
                            int N, int K, int H, int logC) {
    dim3 grid((N + TBN - 1) / TBN, NPAD / TBM);
    h16gemm_kernel<<<grid, 256, GEMM_SMEM>>>(A, Bt, C, a_s, a_d, out_s, out_d,
                                             N, K, H, logC);
}

static inline void run_aggregate(const __half* h, const float* alpha,
                                 const float* inv_,
                                 const int* rowptr, const int* csrsrc,
                                 const float* bias, float* out32,
                                 __half* out16, int H, int HC, int logC) {
    int tx = HC / 4;
    int ty = 256 / tx;
    dim3 block(tx, ty);
    dim3 grid((NN + ty - 1) / ty);
    if (out16)
        aggregate_kernel<true><<<grid, block>>>(h, alpha, inv_, rowptr, csrsrc,
                                                bias, nullptr, out16, H, HC, logC);
    else
        aggregate_kernel<false><<<grid, block>>>(h, alpha, inv_, rowptr, csrsrc,
                                                 bias, out32, nullptr, H, HC, logC);
}

extern "C" void kernel_launch(void* const* d_in, const int* in_sizes, int n_in,
                              void* d_out, int out_size) {
    const float* x   = (const float*)d_in[0];
    const void*  ei  = d_in[1];
    const float* W1  = (const float*)d_in[2];
    const float* a1s = (const float*)d_in[3];
    const float* a1d = (const float*)d_in[4];
    const float* b1  = (const float*)d_in[5];
    const float* W2  = (const float*)d_in[6];
    const float* a2s = (const float*)d_in[7];
    const float* a2d = (const float*)d_in[8];
    const float* b2  = (const float*)d_in[9];
    const float* W3  = (const float*)d_in[10];
    const float* a3s = (const float*)d_in[11];
    const float* a3d = (const float*)d_in[12];
    const float* b3  = (const float*)d_in[13];
    const float* W4  = (const float*)d_in[14];
    const float* a4s = (const float*)d_in[15];
    const float* a4d = (const float*)d_in[16];
    const float* b4  = (const float*)d_in[17];
    float* out = (float*)d_out;

    static cudaStream_t s2 = nullptr;
    static cudaEvent_t evFork = nullptr, evCsr = nullptr;
    static bool inited = false;
    if (!inited) {
        cudaFuncSetAttribute(h16gemm_kernel,
                             cudaFuncAttributeMaxDynamicSharedMemorySize,
                             GEMM_SMEM);
        cudaStreamCreateWithFlags(&s2, cudaStreamNonBlocking);
        cudaEventCreateWithFlags(&evFork, cudaEventDisableTiming);
        cudaEventCreateWithFlags(&evCsr, cudaEventDisableTiming);
        inited = true;
    }

    float *asb, *adb, *invb, *alpha;
    __half *hA, *hB, *wt;
    int *deg, *rowptr, *cursor, *csrsrc, *is64;
    cudaGetSymbolAddress((void**)&hA, g_hA);
    cudaGetSymbolAddress((void**)&hB, g_hB);
    cudaGetSymbolAddress((void**)&wt, g_wt);
    cudaGetSymbolAddress((void**)&asb, g_as);
    cudaGetSymbolAddress((void**)&adb, g_ad);
    cudaGetSymbolAddress((void**)&invb, g_inv);
    cudaGetSymbolAddress((void**)&alpha, g_alpha);
    cudaGetSymbolAddress((void**)&deg, g_deg);
    cudaGetSymbolAddress((void**)&rowptr, g_rowptr);
    cudaGetSymbolAddress((void**)&cursor, g_cursor);
    cudaGetSymbolAddress((void**)&csrsrc, g_csrsrc);
    cudaGetSymbolAddress((void**)&is64, g_is64);

    __half* wt1 = wt;                     // [512][256]
    __half* wt2 = wt + 131072;            // [512][512]
    __half* wt3 = wt + 131072 + 262144;   // [256][512]
    __half* wt4 = wt + 131072 + 262144 + 131072;  // [64][256]

    // ---- fork: CSR build chain on side stream s2 ----
    cudaEventRecord(evFork, 0);
    cudaStreamWaitEvent(s2, evFork, 0);
    cudaMemsetAsync(deg, 0, NN * sizeof(int), s2);
    detect64_kernel<<<1, 32, 0, s2>>>((const int*)ei, is64);
    count_deg_kernel<<<(E_TOT + 255) / 256, 256, 0, s2>>>(ei, is64, deg);
    scan_kernel<<<1, 1024, 0, s2>>>(deg, rowptr, cursor, NN);
    fill_csr_kernel<<<(E_TOT + 255) / 256, 256, 0, s2>>>(ei, is64, cursor, csrsrc);
    cudaEventRecord(evCsr, s2);

    // ---- main stream: conversions + layer-1 GEMM (independent of CSR) ----
    f2h_kernel<<<(NN * 256 / 4 + 255) / 256, 256>>>(x, hA, NN * 256);
    {
        WtJob j1{W1, wt1, 256, 512};
        WtJob j2{W2, wt2, 512, 512};
        WtJob j3{W3, wt3, 512, 256};
        WtJob j4{W4, wt4, 256, 64};
        transpose_all_kernel<<<dim3(16, 16, 4), dim3(32, 8)>>>(j1, j2, j3, j4);
    }

    auto nblocks_warps = [](int warps) { return (warps + 7) / 8; };

    // ---- layer 1: 256 -> 4x128 ----
    run_gemm(hA, wt1, hB, a1s, a1d, asb, adb, 512, 256, 4, 7);
    cudaStreamWaitEvent(0, evCsr, 0);    // join: softmax needs CSR
    edge_softmax4_kernel<<<nblocks_warps(NN), 256>>>(rowptr, csrsrc, asb, adb, alpha, invb);
    run_aggregate(hB, alpha, invb, rowptr, csrsrc, b1, nullptr, hA, 4, 512, 7);

    // ---- layer 2: 512 -> 4x128 ----
    run_gemm(hA, wt2, hB, a2s, a2d, asb, adb, 512, 512, 4, 7);
    edge_softmax4_kernel<<<nblocks_warps(NN), 256>>>(rowptr, csrsrc, asb, adb, alpha, invb);
    run_aggregate(hB, alpha, invb, rowptr, csrsrc, b2, nullptr, hA, 4, 512, 7);

    // ---- layer 3: 512 -> 4x64 ----
    run_gemm(hA, wt3, hB, a3s, a3d, asb, adb, 256, 512, 4, 6);
    edge_softmax4_kernel<<<nblocks_warps(NN), 256>>>(rowptr, csrsrc, asb, adb, alpha, invb);
    run_aggregate(hB, alpha, invb, rowptr, csrsrc, b3, nullptr, hA, 4, 256, 6);

    // ---- layer 4: 256 -> 1x64, concat=False ----
    run_gemm(hA, wt4, hB, a4s, a4d, asb, adb, 64, 256, 1, 6);
    edge_softmax1_kernel<<<nblocks_warps(NN), 256>>>(rowptr, csrsrc, asb, adb, alpha, invb);
    run_aggregate(hB, alpha, invb, rowptr, csrsrc, b4, out, nullptr, 1, 64, 6);

    (void)in_sizes; (void)n_in; (void)out_size;
}

// round 14
// speedup vs baseline: 1.4711x; 1.0278x over previous
#include <cuda_runtime.h>
#include <cuda_fp16.h>
#include <cstdint>
#include <math.h>

// ---------------------------------------------------------------------------
// GAT 4-layer stack on GB300, round 14 (= round 11 + ldmatrix fragments):
//  - GEMM mainloop fragment loads via ldmatrix.m8n8.x4 (48 LDS -> 12 LDSM
//    per K-iter per warp). tcgen05 is unavailable (harness targets sm_103).
//  - everything else identical to the 439.7us round-11 kernel.
// ---------------------------------------------------------------------------

#define NN      30000
#define NPAD    30080
#define E_RAW   480000
#define E_TOT   (E_RAW + NN)
#define MAXF    512
#define NEG_SLOPE 0.2f

// ---- scratch (device globals; zero-initialized at load) -------------------
__device__ __half g_hA[NPAD * MAXF];            // fp16 activations ping
__device__ __half g_hB[NPAD * MAXF];            // fp16 activations pong
__device__ __half g_wt[540672];                 // transposed fp16 weights
__device__ float  g_as[NN * 4];
__device__ float  g_ad[NN * 4];
__device__ float  g_inv[NN * 4];                // 1/den per (dst,head)
__device__ float  g_alpha[(size_t)E_TOT * 4];   // unnormalized exp weights
__device__ int    g_deg[NN];
__device__ int    g_rowptr[NN + 1];
__device__ int    g_cursor[NN];
__device__ int    g_csrsrc[E_TOT];
__device__ int    g_is64;

// ---------------------------------------------------------------------------
// edge_index dtype detection (int32 vs int64)
// ---------------------------------------------------------------------------
__global__ void detect64_kernel(const int* __restrict__ words, int* flag) {
    if (threadIdx.x == 0 && blockIdx.x == 0) {
        int any = 0;
        #pragma unroll 4
        for (int i = 0; i < 256; i++) any |= words[2 * i + 1];
        *flag = (any == 0) ? 1 : 0;
    }
}

__device__ __forceinline__ void get_edge(const void* ei, int e, int is64,
                                         int& src, int& dst) {
    if (e >= E_RAW) { src = dst = e - E_RAW; return; }
    if (is64) {
        const long long* p = (const long long*)ei;
        src = (int)p[e];
        dst = (int)p[E_RAW + e];
    } else {
        const int* p = (const int*)ei;
        src = p[e];
        dst = p[E_RAW + e];
    }
}

// ---- CSR build ------------------------------------------------------------
__global__ void count_deg_kernel(const void* __restrict__ ei,
                                 const int* __restrict__ flag,
                                 int* __restrict__ deg) {
    int e = blockIdx.x * blockDim.x + threadIdx.x;
    if (e >= E_TOT) return;
    int src, dst;
    get_edge(ei, e, *flag, src, dst);
    atomicAdd(&deg[dst], 1);
}

// shuffle-based block scan; writes rowptr AND cursor (exclusive prefix)
__global__ void scan_kernel(const int* __restrict__ deg,
                            int* __restrict__ rowptr,
                            int* __restrict__ cursor, int n) {
    __shared__ int warpsums[32];
    __shared__ int carry_s;
    int t = threadIdx.x;
    int lane = t & 31;
    int w = t >> 5;
    if (t == 0) carry_s = 0;
    __syncthreads();
    for (int base = 0; base < n; base += 1024) {
        int i = base + t;
        int v = (i < n) ? deg[i] : 0;
        int x = v;
        #pragma unroll
        for (int o = 1; o < 32; o <<= 1) {
            int u = __shfl_up_sync(0xffffffffu, x, o);
            if (lane >= o) x += u;
        }
        if (lane == 31) warpsums[w] = x;
        __syncthreads();
        if (w == 0) {
            int s = warpsums[lane];
            #pragma unroll
            for (int o = 1; o < 32; o <<= 1) {
                int u = __shfl_up_sync(0xffffffffu, s, o);
                if (lane >= o) s += u;
            }
            warpsums[lane] = s;
        }
        __syncthreads();
        int woff = (w > 0) ? warpsums[w - 1] : 0;
        int incl = x + woff + carry_s;
        if (i < n) {
            int ex = incl - v;
            rowptr[i] = ex;
            cursor[i] = ex;
        }
        __syncthreads();
        if (t == 1023) carry_s = incl;
        __syncthreads();
    }
    if (t == 0) rowptr[n] = carry_s;
}

__global__ void fill_csr_kernel(const void* __restrict__ ei,
                                const int* __restrict__ flag,
                                int* __restrict__ cursor,
                                int* __restrict__ csrsrc) {
    int e = blockIdx.x * blockDim.x + threadIdx.x;
    if (e >= E_TOT) return;
    int src, dst;
    get_edge(ei, e, *flag, src, dst);
    int pos = atomicAdd(&cursor[dst], 1);
    csrsrc[pos] = src;
}

// ---- prep: fp32 -> fp16 convert, fused weight transposes ------------------
__global__ void f2h_kernel(const float* __restrict__ in,
                           __half* __restrict__ out, int n) {
    int i = blockIdx.x * blockDim.x + threadIdx.x;
    int i4 = i * 4;
    if (i4 + 3 < n) {
        float4 v = *(const float4*)&in[i4];
        *(__half2*)&out[i4] = __floats2half2_rn(v.x, v.y);
        *(__half2*)&out[i4 + 2] = __floats2half2_rn(v.z, v.w);
    } else {
        for (int j = i4; j < n; j++) out[j] = __float2half_rn(in[j]);
    }
}

struct WtJob { const float* W; __half* Wt; int K, N; };

__global__ void transpose_all_kernel(WtJob j0, WtJob j1, WtJob j2, WtJob j3) {
    WtJob j = (blockIdx.z == 0) ? j0 : (blockIdx.z == 1) ? j1
            : (blockIdx.z == 2) ? j2 : j3;
    int k0 = blockIdx.y * 32, n0 = blockIdx.x * 32;
    if (k0 >= j.K || n0 >= j.N) return;
    __shared__ float tile[32][33];
    int tx = threadIdx.x, ty = threadIdx.y;
    for (int i = ty; i < 32; i += 8) {
        int k = k0 + i, n = n0 + tx;
        tile[i][tx] = (k < j.K && n < j.N) ? j.W[(size_t)k * j.N + n] : 0.f;
    }
    __syncthreads();
    for (int i = ty; i < 32; i += 8) {
        int n = n0 + i, k = k0 + tx;
        if (n < j.N && k < j.K)
            j.Wt[(size_t)n * j.K + k] = __float2half_rn(tile[tx][i]);
    }
}

// ---------------------------------------------------------------------------
// fp16 tensor-core GEMM + fused attention-logit epilogue.
// 3-stage cp.async pipeline, dynamic smem, ldmatrix fragment loads.
// ---------------------------------------------------------------------------
#define TBM 128
#define TBN 128
#define TBK 32
#define SAH 40
#define GEMM_SMEM (3 * (TBM + TBN) * SAH * 2)   // 61440 bytes

__device__ __forceinline__ void cp16(unsigned int smem, const void* gptr, int sz) {
    asm volatile("cp.async.cg.shared.global [%0], [%1], 16, %2;\n"
                 :: "r"(smem), "l"(gptr), "r"(sz));
}

__device__ __forceinline__ unsigned int smem_u32(const void* p) {
    return (unsigned int)__cvta_generic_to_shared(p);
}

__device__ __forceinline__ void ldsm_x4(unsigned& r0, unsigned& r1,
                                        unsigned& r2, unsigned& r3,
                                        unsigned addr) {
    asm volatile("ldmatrix.sync.aligned.m8n8.x4.shared.b16 {%0,%1,%2,%3}, [%4];"
                 : "=r"(r0), "=r"(r1), "=r"(r2), "=r"(r3) : "r"(addr));
}

__device__ __forceinline__ void mma_f16(float* d, const unsigned* a,
                                        const unsigned* b) {
    asm volatile(
        "mma.sync.aligned.m16n8k16.row.col.f32.f16.f16.f32 "
        "{%0,%1,%2,%3}, {%4,%5,%6,%7}, {%8,%9}, {%0,%1,%2,%3};\n"
        : "+f"(d[0]), "+f"(d[1]), "+f"(d[2]), "+f"(d[3])
        : "r"(a[0]), "r"(a[1]), "r"(a[2]), "r"(a[3]),
          "r"(b[0]), "r"(b[1]));
}

__global__ __launch_bounds__(256, 2)
void h16gemm_kernel(const __half* __restrict__ A, const __half* __restrict__ Bt,
                    __half* __restrict__ C,
                    const float* __restrict__ a_s, const float* __restrict__ a_d,
                    float* __restrict__ out_s, float* __restrict__ out_d,
                    int N, int K, int H, int logC) {
    extern __shared__ __align__(16) char dsm[];
    __half* As = (__half*)dsm;                  // [3][TBM*SAH]
    __half* Bs = As + 3 * TBM * SAH;            // [3][TBN*SAH]
    float* s_av  = (float*)dsm;                 // [2][TBN]  (epilogue alias)
    float* tmp_s = s_av + 2 * TBN;              // [4][128]
    float* tmp_d = tmp_s + 4 * 128;             // [4][128]

    int tid  = threadIdx.x;
    int bm   = blockIdx.y * TBM;
    int bn   = blockIdx.x * TBN;
    int warp = tid >> 5;
    int lane = tid & 31;
    int wm   = (warp & 1) * 64;
    int wn   = (warp >> 1) * 32;
    int wnq  = warp >> 1;
    int r    = lane >> 2;
    int c    = lane & 3;

    // ldmatrix lane addressing
    int q  = lane >> 3;           // matrix id 0..3
    int j  = lane & 7;            // row within matrix
    int a_row = j + (q & 1) * 8;  // A: +8 rows for a1/a3
    int a_kof = (q >> 1) * 8;     // A: +8 k for a2/a3
    int b_row = (q >> 1) * 8 + j; // B: +8 n-rows for second ni of pair
    int b_kof = (q & 1) * 8;      // B: +8 k for b1

    float acc[4][4][4];
    #pragma unroll
    for (int mi = 0; mi < 4; mi++)
        #pragma unroll
        for (int ni = 0; ni < 4; ni++)
            #pragma unroll
            for (int qq = 0; qq < 4; qq++) acc[mi][ni][qq] = 0.f;

    int row0 = tid >> 1;
    int kc0  = (tid & 1) * 2;
    int niter = K / TBK;

    auto stage = [&](int buf, int k0) {
        #pragma unroll
        for (int jj = 0; jj < 2; jj++) {
            int kc = kc0 + jj;
            int smoff = (row0 * SAH + kc * 8) * 2;
            const __half* ga = A + (size_t)(bm + row0) * K + k0 + kc * 8;
            cp16(smem_u32(&As[buf * TBM * SAH]) + smoff, ga, 16);
            int rb = bn + row0;
            const __half* gb = Bt + (size_t)(rb < N ? rb : 0) * K + k0 + kc * 8;
            cp16(smem_u32(&Bs[buf * TBN * SAH]) + smoff, gb, rb < N ? 16 : 0);
        }
        asm volatile("cp.async.commit_group;\n");
    };

    stage(0, 0);
    stage(1, TBK);

    for (int it = 0; it < niter; it++) {
        if (it < niter - 1) {
            asm volatile("cp.async.wait_group 1;\n");
        } else {
            asm volatile("cp.async.wait_group 0;\n");
        }
        __syncthreads();
        if (it + 2 < niter) stage((it + 2) % 3, (it + 2) * TBK);

        int buf = it % 3;
        const __half* Ab = &As[buf * TBM * SAH];
        const __half* Bb = &Bs[buf * TBN * SAH];
        #pragma unroll
        for (int kk = 0; kk < 2; kk++) {
            int kb = kk * 16;
            unsigned af[4][4];
            #pragma unroll
            for (int mi = 0; mi < 4; mi++) {
                unsigned addr = smem_u32(
                    Ab + (wm + mi * 16 + a_row) * SAH + kb + a_kof);
                ldsm_x4(af[mi][0], af[mi][1], af[mi][2], af[mi][3], addr);
            }
            unsigned bf[4][2];
            #pragma unroll
            for (int ni = 0; ni < 4; ni += 2) {
                unsigned addr = smem_u32(
                    Bb + (wn + ni * 8 + b_row) * SAH + kb + b_kof);
                ldsm_x4(bf[ni][0], bf[ni][1], bf[ni + 1][0], bf[ni + 1][1], addr);
            }
            #pragma unroll
            for (int mi = 0; mi < 4; mi++)
                #pragma unroll
                for (int ni = 0; ni < 4; ni++)
                    mma_f16(acc[mi][ni], af[mi], bf[ni]);
        }
    }
    __syncthreads();   // all compute done before epilogue aliases smem

    // ---- store h (fp16) ----
    #pragma unroll
    for (int mi = 0; mi < 4; mi++) {
        int m0 = bm + wm + mi * 16 + r;
        #pragma unroll
        for (int ni = 0; ni < 4; ni++) {
            int n0 = bn + wn + ni * 8 + 2 * c;
            if (n0 < N) {
                __half2 v0 = __floats2half2_rn(acc[mi][ni][0], acc[mi][ni][1]);
                *(__half2*)&C[(size_t)m0 * N + n0] = v0;
                __half2 v1 = __floats2half2_rn(acc[mi][ni][2], acc[mi][ni][3]);
                *(__half2*)&C[(size_t)(m0 + 8) * N + n0] = v1;
            }
        }
    }

    // ---- fused logits ----
    if (tid < TBN) {
        int gcol = bn + tid;
        s_av[tid] = (gcol < N) ? a_s[gcol] : 0.f;
    } else {
        int gcol = bn + tid - TBN;
        s_av[TBN + tid - TBN] = (gcol < N) ? a_d[gcol] : 0.f;
    }
    __syncthreads();

    float ps[4][2], pd[4][2];
    #pragma unroll
    for (int mi = 0; mi < 4; mi++) {
        ps[mi][0] = ps[mi][1] = 0.f;
        pd[mi][0] = pd[mi][1] = 0.f;
    }
    #pragma unroll
    for (int mi = 0; mi < 4; mi++)
        #pragma unroll
        for (int ni = 0; ni < 4; ni++)
            #pragma unroll
            for (int qq = 0; qq < 4; qq++) {
                int col = wn + ni * 8 + 2 * c + (qq & 1);
                int hf = qq >> 1;
                ps[mi][hf] = fmaf(acc[mi][ni][qq], s_av[col], ps[mi][hf]);
                pd[mi][hf] = fmaf(acc[mi][ni][qq], s_av[TBN + col], pd[mi][hf]);
            }
    #pragma unroll
    for (int mi = 0; mi < 4; mi++)
        #pragma unroll
        for (int hf = 0; hf < 2; hf++) {
            float vs = ps[mi][hf], vd = pd[mi][hf];
            vs += __shfl_xor_sync(0xffffffffu, vs, 1);
            vs += __shfl_xor_sync(0xffffffffu, vs, 2);
            vd += __shfl_xor_sync(0xffffffffu, vd, 1);
            vd += __shfl_xor_sync(0xffffffffu, vd, 2);
            if (c == 0) {
                int row = wm + mi * 16 + r + hf * 8;
                tmp_s[wnq * 128 + row] = vs;
                tmp_d[wnq * 128 + row] = vd;
            }
        }
    __syncthreads();

    int hpb = TBN >> logC;
    int gph = 4 / hpb;
    if (tid < 128) {
        int row = tid, n = bm + row;
        if (n < NN) {
            for (int hl = 0; hl < hpb; hl++) {
                int colbase = hl << logC;
                if (bn + colbase < N) {
                    float sum = 0.f;
                    for (int g = 0; g < gph; g++)
                        sum += tmp_s[(hl * gph + g) * 128 + row];
                    int head = (bn + colbase) >> logC;
                    out_s[n * H + head] = sum;
                }
            }
        }
    } else {
        int row = tid - 128, n = bm + row;
        if (n < NN) {
            for (int hl = 0; hl < hpb; hl++) {
                int colbase = hl << logC;
                if (bn + colbase < N) {
                    float sum = 0.f;
                    for (int g = 0; g < gph; g++)
                        sum += tmp_d[(hl * gph + g) * 128 + row];
                    int head = (bn + colbase) >> logC;
                    out_d[n * H + head] = sum;
                }
            }
        }
    }
}

// ---- head-combined edge softmax (2 passes; inv stored) --------------------
__device__ __forceinline__ float leaky(float x) {
    return x > 0.f ? x : NEG_SLOPE * x;
}

__global__ __launch_bounds__(256)
void edge_softmax4_kernel(const int* __restrict__ rowptr,
                          const int* __restrict__ csrsrc,
                          const float* __restrict__ as_,
                          const float* __restrict__ ad_,
                          float* __restrict__ alpha,
                          float* __restrict__ inv_) {
    int d = (blockIdx.x * blockDim.x + threadIdx.x) >> 5;
    int lane = threadIdx.x & 31;
    if (d >= NN) return;
    int s0 = rowptr[d], s1 = rowptr[d + 1];
    float4 ad4 = *(const float4*)&ad_[d * 4];

    float4 mx = make_float4(-3e38f, -3e38f, -3e38f, -3e38f);
    for (int p = s0 + lane; p < s1; p += 32) {
        int src = csrsrc[p];
        float4 g = *(const float4*)&as_[src * 4];
        float4 e;
        e.x = leaky(g.x + ad4.x);
        e.y = leaky(g.y + ad4.y);
        e.z = leaky(g.z + ad4.z);
        e.w = leaky(g.w + ad4.w);
        *(float4*)&alpha[(size_t)p * 4] = e;
        mx.x = fmaxf(mx.x, e.x); mx.y = fmaxf(mx.y, e.y);
        mx.z = fmaxf(mx.z, e.z); mx.w = fmaxf(mx.w, e.w);
    }
    #pragma unroll
    for (int o = 16; o > 0; o >>= 1) {
        mx.x = fmaxf(mx.x, __shfl_xor_sync(0xffffffffu, mx.x, o));
        mx.y = fmaxf(mx.y, __shfl_xor_sync(0xffffffffu, mx.y, o));
        mx.z = fmaxf(mx.z, __shfl_xor_sync(0xffffffffu, mx.z, o));
        mx.w = fmaxf(mx.w, __shfl_xor_sync(0xffffffffu, mx.w, o));
    }

    float4 sum = make_float4(0.f, 0.f, 0.f, 0.f);
    for (int p = s0 + lane; p < s1; p += 32) {
        float4 e = *(const float4*)&alpha[(size_t)p * 4];
        float4 ex;
        ex.x = expf(e.x - mx.x); ex.y = expf(e.y - mx.y);
        ex.z = expf(e.z - mx.z); ex.w = expf(e.w - mx.w);
        *(float4*)&alpha[(size_t)p * 4] = ex;
        sum.x += ex.x; sum.y += ex.y; sum.z += ex.z; sum.w += ex.w;
    }
    #pragma unroll
    for (int o = 16; o > 0; o >>= 1) {
        sum.x += __shfl_xor_sync(0xffffffffu, sum.x, o);
        sum.y += __shfl_xor_sync(0xffffffffu, sum.y, o);
        sum.z += __shfl_xor_sync(0xffffffffu, sum.z, o);
        sum.w += __shfl_xor_sync(0xffffffffu, sum.w, o);
    }
    if (lane == 0) {
        float4 inv;
        inv.x = 1.f / sum.x; inv.y = 1.f / sum.y;
        inv.z = 1.f / sum.z; inv.w = 1.f / sum.w;
        *(float4*)&inv_[d * 4] = inv;
    }
}

__global__ __launch_bounds__(256)
void edge_softmax1_kernel(const int* __restrict__ rowptr,
                          const int* __restrict__ csrsrc,
                          const float* __restrict__ as_,
                          const float* __restrict__ ad_,
                          float* __restrict__ alpha,
                          float* __restrict__ inv_) {
    int d = (blockIdx.x * blockDim.x + threadIdx.x) >> 5;
    int lane = threadIdx.x & 31;
    if (d >= NN) return;
    int s0 = rowptr[d], s1 = rowptr[d + 1];
    float adv = ad_[d];

    float mx = -3e38f;
    for (int p = s0 + lane; p < s1; p += 32) {
        float e = leaky(as_[csrsrc[p]] + adv);
        alpha[p] = e;
        mx = fmaxf(mx, e);
    }
    #pragma unroll
    for (int o = 16; o > 0; o >>= 1)
        mx = fmaxf(mx, __shfl_xor_sync(0xffffffffu, mx, o));

    float sum = 0.f;
    for (int p = s0 + lane; p < s1; p += 32) {
        float ex = expf(alpha[p] - mx);
        alpha[p] = ex;
        sum += ex;
    }
    #pragma unroll
    for (int o = 16; o > 0; o >>= 1)
        sum += __shfl_xor_sync(0xffffffffu, sum, o);
    if (lane == 0) inv_[d] = 1.f / sum;
}

// ---- aggregation: out = relu(inv * sum ex*h16 + b); 4-edge unroll ---------
template <bool F16OUT>
__global__ __launch_bounds__(256)
void aggregate_kernel(const __half* __restrict__ h,
                      const float* __restrict__ alpha,
                      const float* __restrict__ inv_,
                      const int* __restrict__ rowptr,
                      const int* __restrict__ csrsrc,
                      const float* __restrict__ bias,
                      float* __restrict__ out32,
                      __half* __restrict__ out16,
                      int H, int HC, int logC) {
    int d = blockIdx.x * blockDim.y + threadIdx.y;
    if (d >= NN) return;
    int f = threadIdx.x * 4;
    int head = f >> logC;

    float acc0 = 0.f, acc1 = 0.f, acc2 = 0.f, acc3 = 0.f;
    int s0 = rowptr[d], s1 = rowptr[d + 1];
    int p = s0;
    for (; p + 3 < s1; p += 4) {
        int sA = csrsrc[p],     sB = csrsrc[p + 1];
        int sC = csrsrc[p + 2], sD = csrsrc[p + 3];
        float aA = alpha[(size_t)p * H + head];
        float aB = alpha[(size_t)(p + 1) * H + head];
        float aC = alpha[(size_t)(p + 2) * H + head];
        float aD = alpha[(size_t)(p + 3) * H + head];
        uint2 rA = *(const uint2*)&h[(size_t)sA * HC + f];
        uint2 rB = *(const uint2*)&h[(size_t)sB * HC + f];
        uint2 rC = *(const uint2*)&h[(size_t)sC * HC + f];
        uint2 rD = *(const uint2*)&h[(size_t)sD * HC + f];
        float2 vA0 = __half22float2(*(__half2*)&rA.x);
        float2 vA1 = __half22float2(*(__half2*)&rA.y);
        float2 vB0 = __half22float2(*(__half2*)&rB.x);
        float2 vB1 = __half22float2(*(__half2*)&rB.y);
        float2 vC0 = __half22float2(*(__half2*)&rC.x);
        float2 vC1 = __half22float2(*(__half2*)&rC.y);
        float2 vD0 = __half22float2(*(__half2*)&rD.x);
        float2 vD1 = __half22float2(*(__half2*)&rD.y);
        acc0 = fmaf(vA0.x, aA, fmaf(vB0.x, aB, fmaf(vC0.x, aC, fmaf(vD0.x, aD, acc0))));
        acc1 = fmaf(vA0.y, aA, fmaf(vB0.y, aB, fmaf(vC0.y, aC, fmaf(vD0.y, aD, acc1))));
        acc2 = fmaf(vA1.x, aA, fmaf(vB1.x, aB, fmaf(vC1.x, aC, fmaf(vD1.x, aD, acc2))));
        acc3 = fmaf(vA1.y, aA, fmaf(vB1.y, aB, fmaf(vC1.y, aC, fmaf(vD1.y, aD, acc3))));
    }
    for (; p < s1; p++) {
        int src = csrsrc[p];
        float a = alpha[(size_t)p * H + head];
        uint2 raw = *(const uint2*)&h[(size_t)src * HC + f];
        float2 v0 = __half22float2(*(__half2*)&raw.x);
        float2 v1 = __half22float2(*(__half2*)&raw.y);
        acc0 = fmaf(v0.x, a, acc0);
        acc1 = fmaf(v0.y, a, acc1);
        acc2 = fmaf(v1.x, a, acc2);
        acc3 = fmaf(v1.y, a, acc3);
    }

    float inv = inv_[d * H + head];
    float4 b = *(const float4*)&bias[f];
    float o0 = fmaxf(fmaf(acc0, inv, b.x), 0.f);
    float o1 = fmaxf(fmaf(acc1, inv, b.y), 0.f);
    float o2 = fmaxf(fmaf(acc2, inv, b.z), 0.f);
    float o3 = fmaxf(fmaf(acc3, inv, b.w), 0.f);
    if (F16OUT) {
        uint2 packed;
        *(__half2*)&packed.x = __floats2half2_rn(o0, o1);
        *(__half2*)&packed.y = __floats2half2_rn(o2, o3);
        *(uint2*)&out16[(size_t)d * HC + f] = packed;
    } else {
        float4 o = make_float4(o0, o1, o2, o3);
        *(float4*)&out32[(size_t)d * HC + f] = o;
    }
}

// ---------------------------------------------------------------------------
// host side
// ---------------------------------------------------------------------------
static inline void run_gemm(const __half* A, const __half* Bt, __half* C,
                            const float* a_s, const float* a_d,
                            float* out_s, float* out_d,
                            int N, int K, int H, int logC) {
    dim3 grid((N + TBN - 1) / TBN, NPAD / TBM);
    h16gemm_kernel<<<grid, 256, GEMM_SMEM>>>(A, Bt, C, a_s, a_d, out_s, out_d,
                                             N, K, H, logC);
}

static inline void run_aggregate(const __half* h, const float* alpha,
                                 const float* inv_,
                                 const int* rowptr, const int* csrsrc,
                                 const float* bias, float* out32,
                                 __half* out16, int H, int HC, int logC) {
    int tx = HC / 4;
    int ty = 256 / tx;
    dim3 block(tx, ty);
    dim3 grid((NN + ty - 1) / ty);
    if (out16)
        aggregate_kernel<true><<<grid, block>>>(h, alpha, inv_, rowptr, csrsrc,
                                                bias, nullptr, out16, H, HC, logC);
    else
        aggregate_kernel<false><<<grid, block>>>(h, alpha, inv_, rowptr, csrsrc,
                                                 bias, out32, nullptr, H, HC, logC);
}

extern "C" void kernel_launch(void* const* d_in, const int* in_sizes, int n_in,
                              void* d_out, int out_size) {
    const float* x   = (const float*)d_in[0];
    const void*  ei  = d_in[1];
    const float* W1  = (const float*)d_in[2];
    const float* a1s = (const float*)d_in[3];
    const float* a1d = (const float*)d_in[4];
    const float* b1  = (const float*)d_in[5];
    const float* W2  = (const float*)d_in[6];
    const float* a2s = (const float*)d_in[7];
    const float* a2d = (const float*)d_in[8];
    const float* b2  = (const float*)d_in[9];
    const float* W3  = (const float*)d_in[10];
    const float* a3s = (const float*)d_in[11];
    const float* a3d = (const float*)d_in[12];
    const float* b3  = (const float*)d_in[13];
    const float* W4  = (const float*)d_in[14];
    const float* a4s = (const float*)d_in[15];
    const float* a4d = (const float*)d_in[16];
    const float* b4  = (const float*)d_in[17];
    float* out = (float*)d_out;

    static cudaStream_t s2 = nullptr;
    static cudaEvent_t evFork = nullptr, evCsr = nullptr;
    static bool inited = false;
    if (!inited) {
        cudaFuncSetAttribute(h16gemm_kernel,
                             cudaFuncAttributeMaxDynamicSharedMemorySize,
                             GEMM_SMEM);
        cudaStreamCreateWithFlags(&s2, cudaStreamNonBlocking);
        cudaEventCreateWithFlags(&evFork, cudaEventDisableTiming);
        cudaEventCreateWithFlags(&evCsr, cudaEventDisableTiming);
        inited = true;
    }

    float *asb, *adb, *invb, *alpha;
    __half *hA, *hB, *wt;
    int *deg, *rowptr, *cursor, *csrsrc, *is64;
    cudaGetSymbolAddress((void**)&hA, g_hA);
    cudaGetSymbolAddress((void**)&hB, g_hB);
    cudaGetSymbolAddress((void**)&wt, g_wt);
    cudaGetSymbolAddress((void**)&asb, g_as);
    cudaGetSymbolAddress((void**)&adb, g_ad);
    cudaGetSymbolAddress((void**)&invb, g_inv);
    cudaGetSymbolAddress((void**)&alpha, g_alpha);
    cudaGetSymbolAddress((void**)&deg, g_deg);
    cudaGetSymbolAddress((void**)&rowptr, g_rowptr);
    cudaGetSymbolAddress((void**)&cursor, g_cursor);
    cudaGetSymbolAddress((void**)&csrsrc, g_csrsrc);
    cudaGetSymbolAddress((void**)&is64, g_is64);

    __half* wt1 = wt;                     // [512][256]
    __half* wt2 = wt + 131072;            // [512][512]
    __half* wt3 = wt + 131072 + 262144;   // [256][512]
    __half* wt4 = wt + 131072 + 262144 + 131072;  // [64][256]

    // ---- fork: CSR build chain on side stream s2 ----
    cudaEventRecord(evFork, 0);
    cudaStreamWaitEvent(s2, evFork, 0);
    cudaMemsetAsync(deg, 0, NN * sizeof(int), s2);
    detect64_kernel<<<1, 32, 0, s2>>>((const int*)ei, is64);
    count_deg_kernel<<<(E_TOT + 255) / 256, 256, 0, s2>>>(ei, is64, deg);
    scan_kernel<<<1, 1024, 0, s2>>>(deg, rowptr, cursor, NN);
    fill_csr_kernel<<<(E_TOT + 255) / 256, 256, 0, s2>>>(ei, is64, cursor, csrsrc);
    cudaEventRecord(evCsr, s2);

    // ---- main stream: conversions + layer-1 GEMM ----
    f2h_kernel<<<(NN * 256 / 4 + 255) / 256, 256>>>(x, hA, NN * 256);
    {
        WtJob j1{W1, wt1, 256, 512};
        WtJob j2{W2, wt2, 512, 512};
        WtJob j3{W3, wt3, 512, 256};
        WtJob j4{W4, wt4, 256, 64};
        transpose_all_kernel<<<dim3(16, 16, 4), dim3(32, 8)>>>(j1, j2, j3, j4);
    }

    auto nblocks_warps = [](int warps) { return (warps + 7) / 8; };

    // ---- layer 1: 256 -> 4x128 ----
    run_gemm(hA, wt1, hB, a1s, a1d, asb, adb, 512, 256, 4, 7);
    cudaStreamWaitEvent(0, evCsr, 0);
    edge_softmax4_kernel<<<nblocks_warps(NN), 256>>>(rowptr, csrsrc, asb, adb, alpha, invb);
    run_aggregate(hB, alpha, invb, rowptr, csrsrc, b1, nullptr, hA, 4, 512, 7);

    // ---- layer 2: 512 -> 4x128 ----
    run_gemm(hA, wt2, hB, a2s, a2d, asb, adb, 512, 512, 4, 7);
    edge_softmax4_kernel<<<nblocks_warps(NN), 256>>>(rowptr, csrsrc, asb, adb, alpha, invb);
    run_aggregate(hB, alpha, invb, rowptr, csrsrc, b2, nullptr, hA, 4, 512, 7);

    // ---- layer 3: 512 -> 4x64 ----
    run_gemm(hA, wt3, hB, a3s, a3d, asb, adb, 256, 512, 4, 6);
    edge_softmax4_kernel<<<nblocks_warps(NN), 256>>>(rowptr, csrsrc, asb, adb, alpha, invb);
    run_aggregate(hB, alpha, invb, rowptr, csrsrc, b3, nullptr, hA, 4, 256, 6);

    // ---- layer 4: 256 -> 1x64, concat=False ----
    run_gemm(hA, wt4, hB, a4s, a4d, asb, adb, 64, 256, 1, 6);
    edge_softmax1_kernel<<<nblocks_warps(NN), 256>>>(rowptr, csrsrc, asb, adb, alpha, invb);
    run_aggregate(hB, alpha, invb, rowptr, csrsrc, b4, out, nullptr, 1, 64, 6);

    (void)in_sizes; (void)n_in; (void)out_size;
}